// round 2
// baseline (speedup 1.0000x reference)
#include <cuda_runtime.h>
#include <math.h>

#define TOKENS  2048
#define HIDDEN  2048
#define INTER   1408
#define EXPERTS 16
#define TOPK    2
#define MAXPAIRS (TOKENS*TOPK)

// ---------------- scratch (static device globals; no allocation) ----------------
__device__ int   g_cnt[EXPERTS];
__device__ int   g_off[EXPERTS + 1];
__device__ int   g_tok[EXPERTS * TOKENS];     // token id per (expert, local slot)
__device__ int   g_te[MAXPAIRS];              // expert id per (token, k)
__device__ int   g_tslot[MAXPAIRS];           // local slot per (token, k)
__device__ float g_tw[MAXPAIRS];              // routing weight per (token, k)
__device__ float g_logits[TOKENS * EXPERTS];
__device__ float g_gate[(size_t)MAXPAIRS * INTER];   // gate proj, then h (in place)
__device__ float g_up[(size_t)MAXPAIRS * INTER];
__device__ float g_y[(size_t)MAXPAIRS * HIDDEN];     // per-pair down-proj output

// ---------------- tiny helpers ----------------
__device__ __forceinline__ float sigmoidf_fast(float x) {
    return 1.0f / (1.0f + __expf(-x));
}

// ---------------- kernel 1: zero counters ----------------
__global__ void zero_cnt_kernel() {
    if (threadIdx.x < EXPERTS) g_cnt[threadIdx.x] = 0;
}

// ---------------- kernel 2: router logits  logits[t][e] = X[t] . Wg[:,e] ----------
__global__ void router_logits_kernel(const float* __restrict__ X,
                                     const float* __restrict__ Wg) {
    int idx = blockIdx.x * blockDim.x + threadIdx.x;   // TOKENS*EXPERTS threads
    int t = idx >> 4;
    int e = idx & 15;
    const float* xr = X + (size_t)t * HIDDEN;
    float s0 = 0.f, s1 = 0.f, s2 = 0.f, s3 = 0.f;
    #pragma unroll 4
    for (int k = 0; k < HIDDEN; k += 4) {
        s0 = fmaf(xr[k + 0], Wg[(k + 0) * EXPERTS + e], s0);
        s1 = fmaf(xr[k + 1], Wg[(k + 1) * EXPERTS + e], s1);
        s2 = fmaf(xr[k + 2], Wg[(k + 2) * EXPERTS + e], s2);
        s3 = fmaf(xr[k + 3], Wg[(k + 3) * EXPERTS + e], s3);
    }
    g_logits[idx] = (s0 + s1) + (s2 + s3);
}

// ---------------- kernel 3: top-2 (sigmoid monotonic -> top-k on logits) ----------
__global__ void router_topk_kernel() {
    int t = blockIdx.x * blockDim.x + threadIdx.x;
    if (t >= TOKENS) return;
    float l[EXPERTS];
    #pragma unroll
    for (int e = 0; e < EXPERTS; e++) l[e] = g_logits[t * EXPERTS + e];

    // jax.lax.top_k tie rule: earliest index wins -> strict '>' scans
    int e1 = 0; float v1 = l[0];
    #pragma unroll
    for (int e = 1; e < EXPERTS; e++) if (l[e] > v1) { v1 = l[e]; e1 = e; }
    int e2 = -1; float v2 = -3.4e38f;
    #pragma unroll
    for (int e = 0; e < EXPERTS; e++) {
        if (e == e1) continue;
        if (l[e] > v2) { v2 = l[e]; e2 = e; }
    }
    float w1 = sigmoidf_fast(v1);
    float w2 = sigmoidf_fast(v2);
    float inv = 1.0f / (w1 + w2);
    w1 *= inv; w2 *= inv;

    int s1 = atomicAdd(&g_cnt[e1], 1);
    int s2 = atomicAdd(&g_cnt[e2], 1);
    g_tok[e1 * TOKENS + s1] = t;
    g_tok[e2 * TOKENS + s2] = t;
    g_te[2 * t + 0] = e1;  g_tslot[2 * t + 0] = s1;  g_tw[2 * t + 0] = w1;
    g_te[2 * t + 1] = e2;  g_tslot[2 * t + 1] = s2;  g_tw[2 * t + 1] = w2;
}

// ---------------- kernel 4: exclusive prefix of counts ----------------
__global__ void offsets_kernel() {
    if (threadIdx.x == 0 && blockIdx.x == 0) {
        int a = 0;
        for (int e = 0; e < EXPERTS; e++) { g_off[e] = a; a += g_cnt[e]; }
        g_off[EXPERTS] = a;   // == MAXPAIRS
    }
}

// ---------------- grouped GEMM: 128x128 tile, BK=16, 256 thr, 8x8/thread --------
// MODE 0: Out=g_gate, A = gathered X rows (K=HIDDEN, N=INTER)
// MODE 1: Out=g_up,   A = gathered X rows (K=HIDDEN, N=INTER)
// MODE 2: Out=g_y,    A = g_gate rows (h)  (K=INTER,  N=HIDDEN)
template <int MODE>
__global__ __launch_bounds__(256, 2)
void gemm_expert_kernel(const float* __restrict__ X,
                        const float* __restrict__ Wbase) {
    constexpr int Kdim = (MODE == 2) ? INTER : HIDDEN;
    constexpr int Ndim = (MODE == 2) ? HIDDEN : INTER;

    const int e  = blockIdx.z;
    const int ne = g_cnt[e];
    const int m0 = blockIdx.x * 128;
    if (m0 >= ne) return;
    const int n0  = blockIdx.y * 128;
    const int off = g_off[e];
    const float* __restrict__ W = Wbase + (size_t)e * Kdim * Ndim;
    float* __restrict__ Out = (MODE == 0) ? g_gate : (MODE == 1) ? g_up : g_y;

    __shared__ float As[128][16];
    __shared__ float Bs[16][128];

    const int tid = threadIdx.x;
    const int tx  = tid & 15;
    const int ty  = tid >> 4;

    // A-load assignments (fixed across K loop)
    const int lr0 = tid >> 2;            // 0..63
    const int lr1 = lr0 + 64;            // 64..127
    const int c4  = (tid & 3) * 4;       // 0,4,8,12
    const float* a0 = nullptr;
    const float* a1 = nullptr;
    {
        int r = m0 + lr0;
        if (r < ne) {
            if (MODE == 2) a0 = g_gate + (size_t)(off + r) * Kdim;
            else           a0 = X + (size_t)g_tok[e * TOKENS + r] * Kdim;
        }
        r = m0 + lr1;
        if (r < ne) {
            if (MODE == 2) a1 = g_gate + (size_t)(off + r) * Kdim;
            else           a1 = X + (size_t)g_tok[e * TOKENS + r] * Kdim;
        }
    }
    // B-load assignments
    const int brow = tid >> 5;           // 0..7 (second load adds +8)
    const int bc4  = (tid & 31) * 4;     // 0..124

    float acc[8][8];
    #pragma unroll
    for (int i = 0; i < 8; i++)
        #pragma unroll
        for (int j = 0; j < 8; j++) acc[i][j] = 0.f;

    for (int k0 = 0; k0 < Kdim; k0 += 16) {
        float4 va0 = a0 ? *(const float4*)(a0 + k0 + c4) : make_float4(0, 0, 0, 0);
        float4 va1 = a1 ? *(const float4*)(a1 + k0 + c4) : make_float4(0, 0, 0, 0);
        float4 vb0 = *(const float4*)(W + (size_t)(k0 + brow)     * Ndim + n0 + bc4);
        float4 vb1 = *(const float4*)(W + (size_t)(k0 + brow + 8) * Ndim + n0 + bc4);

        __syncthreads();   // previous tile fully consumed
        *(float4*)&As[lr0][c4]      = va0;
        *(float4*)&As[lr1][c4]      = va1;
        *(float4*)&Bs[brow][bc4]     = vb0;
        *(float4*)&Bs[brow + 8][bc4] = vb1;
        __syncthreads();

        #pragma unroll
        for (int kk = 0; kk < 16; kk++) {
            float a[8];
            #pragma unroll
            for (int i = 0; i < 8; i++) a[i] = As[ty * 8 + i][kk];
            float4 bb0 = *(const float4*)&Bs[kk][tx * 4];
            float4 bb1 = *(const float4*)&Bs[kk][tx * 4 + 64];
            float b[8] = {bb0.x, bb0.y, bb0.z, bb0.w, bb1.x, bb1.y, bb1.z, bb1.w};
            #pragma unroll
            for (int i = 0; i < 8; i++)
                #pragma unroll
                for (int j = 0; j < 8; j++)
                    acc[i][j] = fmaf(a[i], b[j], acc[i][j]);
        }
    }

    #pragma unroll
    for (int i = 0; i < 8; i++) {
        int r = m0 + ty * 8 + i;
        if (r < ne) {
            float* o = Out + (size_t)(off + r) * Ndim + n0;
            float4 v0 = make_float4(acc[i][0], acc[i][1], acc[i][2], acc[i][3]);
            float4 v1 = make_float4(acc[i][4], acc[i][5], acc[i][6], acc[i][7]);
            *(float4*)(o + tx * 4)      = v0;
            *(float4*)(o + tx * 4 + 64) = v1;
        }
    }
}

// ---------------- kernel: h = silu(gate) * up, in place into g_gate ----------
__global__ void silu_mul_kernel() {
    size_t idx = (size_t)blockIdx.x * blockDim.x + threadIdx.x;  // MAXPAIRS*INTER/4
    float4 g = *(const float4*)(g_gate + 4 * idx);
    float4 u = *(const float4*)(g_up   + 4 * idx);
    float4 r;
    r.x = g.x * sigmoidf_fast(g.x) * u.x;
    r.y = g.y * sigmoidf_fast(g.y) * u.y;
    r.z = g.z * sigmoidf_fast(g.z) * u.z;
    r.w = g.w * sigmoidf_fast(g.w) * u.w;
    *(float4*)(g_gate + 4 * idx) = r;
}

// ---------------- kernel: out[t] = w0*y[p0] + w1*y[p1] (deterministic) ----------
__global__ void combine_kernel(float* __restrict__ out) {
    int idx = blockIdx.x * blockDim.x + threadIdx.x;   // TOKENS*HIDDEN/4
    int t = idx / (HIDDEN / 4);
    int c = idx % (HIDDEN / 4);
    int e0 = g_te[2 * t], e1 = g_te[2 * t + 1];
    size_t p0 = (size_t)g_off[e0] + g_tslot[2 * t];
    size_t p1 = (size_t)g_off[e1] + g_tslot[2 * t + 1];
    float w0 = g_tw[2 * t], w1 = g_tw[2 * t + 1];
    float4 y0 = *(const float4*)(g_y + p0 * HIDDEN + 4 * c);
    float4 y1 = *(const float4*)(g_y + p1 * HIDDEN + 4 * c);
    float4 r;
    r.x = w0 * y0.x + w1 * y1.x;
    r.y = w0 * y0.y + w1 * y1.y;
    r.z = w0 * y0.z + w1 * y1.z;
    r.w = w0 * y0.w + w1 * y1.w;
    *(float4*)(out + (size_t)t * HIDDEN + 4 * c) = r;
}

// ---------------- launcher ----------------
extern "C" void kernel_launch(void* const* d_in, const int* in_sizes, int n_in,
                              void* d_out, int out_size) {
    const float* X   = (const float*)d_in[0];  // [T, H]
    const float* Wg  = (const float*)d_in[1];  // [H, E]
    const float* Wgp = (const float*)d_in[2];  // [E, H, I]
    const float* Wup = (const float*)d_in[3];  // [E, H, I]
    const float* Wdp = (const float*)d_in[4];  // [E, I, H]
    float* out = (float*)d_out;                // [T, H]

    zero_cnt_kernel<<<1, 32>>>();
    router_logits_kernel<<<(TOKENS * EXPERTS) / 256, 256>>>(X, Wg);
    router_topk_kernel<<<(TOKENS + 255) / 256, 256>>>();
    offsets_kernel<<<1, 1>>>();

    dim3 grid_gu(TOKENS / 128, INTER / 128, EXPERTS);    // (16, 11, 16)
    gemm_expert_kernel<0><<<grid_gu, 256>>>(X, Wgp);
    gemm_expert_kernel<1><<<grid_gu, 256>>>(X, Wup);

    silu_mul_kernel<<<(MAXPAIRS * (INTER / 4)) / 256, 256>>>();

    dim3 grid_dn(TOKENS / 128, HIDDEN / 128, EXPERTS);   // (16, 16, 16)
    gemm_expert_kernel<2><<<grid_dn, 256>>>(nullptr, Wdp);

    combine_kernel<<<(TOKENS * (HIDDEN / 4)) / 256, 256>>>(out);
}

// round 4
// speedup vs baseline: 1.7396x; 1.7396x over previous
#include <cuda_runtime.h>
#include <cstdint>
#include <math.h>

#define TOKENS  2048
#define HIDDEN  2048
#define INTER   1408
#define EXPERTS 16
#define MAXPAIRS (TOKENS*2)

// ---------------- scratch ----------------
__device__ int   g_cnt[EXPERTS];
__device__ int   g_off[EXPERTS + 1];
__device__ int   g_tok[EXPERTS * TOKENS];
__device__ int   g_te[MAXPAIRS];
__device__ int   g_tslot[MAXPAIRS];
__device__ float g_tw[MAXPAIRS];
__device__ float g_logits[TOKENS * EXPERTS];
__device__ float g_gate[(size_t)MAXPAIRS * INTER];   // h = silu(g)*u
__device__ float g_y[(size_t)MAXPAIRS * HIDDEN];

// ---------------- helpers ----------------
__device__ __forceinline__ uint32_t f2tf32(float x) {
    uint32_t r; asm("cvt.rna.tf32.f32 %0, %1;" : "=r"(r) : "f"(x)); return r;
}
__device__ __forceinline__ float sigmoidf_fast(float x) { return 1.0f / (1.0f + __expf(-x)); }

// m16n8k8 tf32 MMA, D += A*B (fp32 accum)
__device__ __forceinline__ void mma8(float* d, const uint32_t* a, const uint32_t* b) {
    asm volatile("mma.sync.aligned.m16n8k8.row.col.f32.tf32.tf32.f32 "
        "{%0,%1,%2,%3}, {%4,%5,%6,%7}, {%8,%9}, {%0,%1,%2,%3};"
        : "+f"(d[0]), "+f"(d[1]), "+f"(d[2]), "+f"(d[3])
        : "r"(a[0]), "r"(a[1]), "r"(a[2]), "r"(a[3]), "r"(b[0]), "r"(b[1]));
}

// ---------------- routing (proven) ----------------
__global__ void zero_cnt_kernel() { if (threadIdx.x < EXPERTS) g_cnt[threadIdx.x] = 0; }

__global__ void router_logits_kernel(const float* __restrict__ X, const float* __restrict__ Wg) {
    int idx = blockIdx.x * blockDim.x + threadIdx.x;
    int t = idx >> 4, e = idx & 15;
    const float* xr = X + (size_t)t * HIDDEN;
    float s0 = 0.f, s1 = 0.f, s2 = 0.f, s3 = 0.f;
    #pragma unroll 4
    for (int k = 0; k < HIDDEN; k += 4) {
        s0 = fmaf(xr[k+0], Wg[(k+0)*EXPERTS + e], s0);
        s1 = fmaf(xr[k+1], Wg[(k+1)*EXPERTS + e], s1);
        s2 = fmaf(xr[k+2], Wg[(k+2)*EXPERTS + e], s2);
        s3 = fmaf(xr[k+3], Wg[(k+3)*EXPERTS + e], s3);
    }
    g_logits[idx] = (s0 + s1) + (s2 + s3);
}

__global__ void router_topk_kernel() {
    int t = blockIdx.x * blockDim.x + threadIdx.x;
    if (t >= TOKENS) return;
    float l[EXPERTS];
    #pragma unroll
    for (int e = 0; e < EXPERTS; e++) l[e] = g_logits[t * EXPERTS + e];
    int e1 = 0; float v1 = l[0];
    #pragma unroll
    for (int e = 1; e < EXPERTS; e++) if (l[e] > v1) { v1 = l[e]; e1 = e; }
    int e2 = -1; float v2 = -3.4e38f;
    #pragma unroll
    for (int e = 0; e < EXPERTS; e++) { if (e == e1) continue; if (l[e] > v2) { v2 = l[e]; e2 = e; } }
    float w1 = sigmoidf_fast(v1), w2 = sigmoidf_fast(v2);
    float inv = 1.0f / (w1 + w2); w1 *= inv; w2 *= inv;
    int s1 = atomicAdd(&g_cnt[e1], 1);
    int s2 = atomicAdd(&g_cnt[e2], 1);
    g_tok[e1 * TOKENS + s1] = t;
    g_tok[e2 * TOKENS + s2] = t;
    g_te[2*t+0] = e1; g_tslot[2*t+0] = s1; g_tw[2*t+0] = w1;
    g_te[2*t+1] = e2; g_tslot[2*t+1] = s2; g_tw[2*t+1] = w2;
}

__global__ void offsets_kernel() {
    if (threadIdx.x == 0 && blockIdx.x == 0) {
        int a = 0;
        for (int e = 0; e < EXPERTS; e++) { g_off[e] = a; a += g_cnt[e]; }
        g_off[EXPERTS] = a;
    }
}

// ---------------- mma.sync grouped GEMM ----------------
// FUSED=1: A = gathered X rows; B0=w_gate_proj, B1=w_up_proj; epi h=silu(g)*u -> g_gate
// FUSED=0: A = g_gate rows (h); B0=w_down_proj; epi raw -> g_y
// CTA tile 128x128, BK=32, warp grid 2(m)x4(n), warp tile 64x32.
template <int FUSED>
__global__ __launch_bounds__(256, 1)
void moe_gemm_mma(const float* __restrict__ X,
                  const float* __restrict__ W0g,
                  const float* __restrict__ W1g) {
    constexpr int Kdim = FUSED ? HIDDEN : INTER;
    constexpr int Ndim = FUSED ? INTER : HIDDEN;
    constexpr int KT   = Kdim / 32;
    constexpr int AW   = 36;                     // A smem row stride (words)
    constexpr int BW   = 136;                    // B smem row stride (words)
    constexpr int OFF_AL = 128 * AW;             // 4608
    constexpr int OFF_B0 = 2 * 128 * AW;         // 9216
    constexpr int OFF_B1 = OFF_B0 + 32 * BW;     // 13568
    constexpr int STAGE  = OFF_B0 + (FUSED ? 2 : 1) * 32 * BW;   // words

    const int e  = blockIdx.z;
    const int ne = g_cnt[e];
    const int m0 = blockIdx.x * 128;
    if (m0 >= ne) return;
    const int n0  = blockIdx.y * 128;
    const int off = g_off[e];

    extern __shared__ uint32_t smw[];

    const int tid  = threadIdx.x;
    const int lane = tid & 31;
    const int wid  = tid >> 5;
    const int wm   = wid & 1;        // 0..1 -> m offset 0/64
    const int wn   = wid >> 1;       // 0..3 -> n offset 0/32/64/96
    const int lg   = lane >> 2;      // group id 0..7
    const int lt   = lane & 3;       // thread-in-group

    // A gather: thread loads row (tid>>1), 16 cols starting at (tid&1)*16
    const float* arow = nullptr;
    {
        int r = m0 + (tid >> 1);
        if (r < ne) arow = FUSED ? X + (size_t)g_tok[e * TOKENS + r] * HIDDEN
                                 : g_gate + (size_t)(off + r) * INTER;
    }
    const int acb  = (tid & 1) * 16;
    const int arsl = tid >> 1;           // local A row for STS
    // B loads: thread loads k-row (tid>>3), 16 cols at (tid&7)*16
    const int bk = tid >> 3;
    const int bn = (tid & 7) * 16;
    const float* w0 = W0g + (size_t)e * Kdim * Ndim + n0;
    const float* w1 = FUSED ? (W1g + (size_t)e * Kdim * Ndim + n0) : nullptr;

    float accG[4][4][4];
    float accU[4][4][4];
    #pragma unroll
    for (int i = 0; i < 4; i++)
        #pragma unroll
        for (int j = 0; j < 4; j++)
            #pragma unroll
            for (int q = 0; q < 4; q++) { accG[i][j][q] = 0.f; if (FUSED) accU[i][j][q] = 0.f; }

    float4 av[4], b0v[4], b1v[4];

    // ---- load tile kt into regs ----
    auto load_tile = [&](int kt) {
        const int k0 = kt * 32;
        #pragma unroll
        for (int f = 0; f < 4; f++)
            av[f] = arow ? *(const float4*)(arow + k0 + acb + 4 * f) : make_float4(0,0,0,0);
        #pragma unroll
        for (int i = 0; i < 4; i++)
            b0v[i] = *(const float4*)(w0 + (size_t)(k0 + bk) * Ndim + bn + 4 * i);
        if (FUSED) {
            #pragma unroll
            for (int i = 0; i < 4; i++)
                b1v[i] = *(const float4*)(w1 + (size_t)(k0 + bk) * Ndim + bn + 4 * i);
        }
    };
    // ---- store regs into smem buffer ----
    auto sts_tile = [&](int buf) {
        uint32_t* sb = smw + buf * STAGE;
        #pragma unroll
        for (int f = 0; f < 4; f++) {
            uint32_t h0 = f2tf32(av[f].x), h1 = f2tf32(av[f].y);
            uint32_t h2 = f2tf32(av[f].z), h3 = f2tf32(av[f].w);
            uint32_t l0 = f2tf32(av[f].x - __uint_as_float(h0));
            uint32_t l1 = f2tf32(av[f].y - __uint_as_float(h1));
            uint32_t l2 = f2tf32(av[f].z - __uint_as_float(h2));
            uint32_t l3 = f2tf32(av[f].w - __uint_as_float(h3));
            int idx = arsl * AW + acb + 4 * f;
            *(uint4*)(sb + idx)          = make_uint4(h0, h1, h2, h3);
            *(uint4*)(sb + OFF_AL + idx) = make_uint4(l0, l1, l2, l3);
        }
        #pragma unroll
        for (int i = 0; i < 4; i++) {
            int idx = bk * BW + bn + 4 * i;
            *(uint4*)(sb + OFF_B0 + idx) = make_uint4(
                f2tf32(b0v[i].x), f2tf32(b0v[i].y), f2tf32(b0v[i].z), f2tf32(b0v[i].w));
            if (FUSED)
                *(uint4*)(sb + OFF_B1 + idx) = make_uint4(
                    f2tf32(b1v[i].x), f2tf32(b1v[i].y), f2tf32(b1v[i].z), f2tf32(b1v[i].w));
        }
    };

    load_tile(0);
    sts_tile(0);
    __syncthreads();

    for (int kt = 0; kt < KT; kt++) {
        const uint32_t* sb = smw + (kt & 1) * STAGE;
        if (kt + 1 < KT) load_tile(kt + 1);

        #pragma unroll
        for (int ks = 0; ks < 4; ks++) {
            // B fragments (conflict-free: bank = 8k+n)
            uint32_t bf0[4][2], bf1[4][2];
            const int kk = ks * 8 + lt;
            #pragma unroll
            for (int nf = 0; nf < 4; nf++) {
                int nn = wn * 32 + nf * 8 + lg;
                bf0[nf][0] = sb[OFF_B0 + kk * BW + nn];
                bf0[nf][1] = sb[OFF_B0 + (kk + 4) * BW + nn];
                if (FUSED) {
                    bf1[nf][0] = sb[OFF_B1 + kk * BW + nn];
                    bf1[nf][1] = sb[OFF_B1 + (kk + 4) * BW + nn];
                }
            }
            #pragma unroll
            for (int mf = 0; mf < 4; mf++) {
                const int r0 = wm * 64 + mf * 16 + lg;
                const int c0 = ks * 8 + lt;
                uint32_t ah[4], al[4];
                ah[0] = sb[r0 * AW + c0];           ah[1] = sb[(r0 + 8) * AW + c0];
                ah[2] = sb[r0 * AW + c0 + 4];       ah[3] = sb[(r0 + 8) * AW + c0 + 4];
                al[0] = sb[OFF_AL + r0 * AW + c0];      al[1] = sb[OFF_AL + (r0 + 8) * AW + c0];
                al[2] = sb[OFF_AL + r0 * AW + c0 + 4];  al[3] = sb[OFF_AL + (r0 + 8) * AW + c0 + 4];
                #pragma unroll
                for (int nf = 0; nf < 4; nf++) {
                    mma8(accG[mf][nf], ah, bf0[nf]);
                    mma8(accG[mf][nf], al, bf0[nf]);
                    if (FUSED) {
                        mma8(accU[mf][nf], ah, bf1[nf]);
                        mma8(accU[mf][nf], al, bf1[nf]);
                    }
                }
            }
        }
        if (kt + 1 < KT) {
            sts_tile((kt + 1) & 1);
            __syncthreads();
        }
    }

    // ---- epilogue ----
    #pragma unroll
    for (int mf = 0; mf < 4; mf++) {
        #pragma unroll
        for (int h = 0; h < 2; h++) {
            int r = m0 + wm * 64 + mf * 16 + lg + h * 8;
            if (r >= ne) continue;
            if (FUSED) {
                float* orow = g_gate + (size_t)(off + r) * INTER + n0 + wn * 32 + lt * 2;
                #pragma unroll
                for (int nf = 0; nf < 4; nf++) {
                    float g0 = accG[mf][nf][2*h],   g1 = accG[mf][nf][2*h+1];
                    float u0 = accU[mf][nf][2*h],   u1 = accU[mf][nf][2*h+1];
                    float2 v;
                    v.x = g0 * sigmoidf_fast(g0) * u0;
                    v.y = g1 * sigmoidf_fast(g1) * u1;
                    *(float2*)(orow + nf * 8) = v;
                }
            } else {
                float* orow = g_y + (size_t)(off + r) * HIDDEN + n0 + wn * 32 + lt * 2;
                #pragma unroll
                for (int nf = 0; nf < 4; nf++) {
                    float2 v = make_float2(accG[mf][nf][2*h], accG[mf][nf][2*h+1]);
                    *(float2*)(orow + nf * 8) = v;
                }
            }
        }
    }
}

// ---------------- combine ----------------
__global__ void combine_kernel(float* __restrict__ out) {
    int idx = blockIdx.x * blockDim.x + threadIdx.x;
    int t = idx / (HIDDEN / 4);
    int c = idx % (HIDDEN / 4);
    int e0 = g_te[2*t], e1 = g_te[2*t+1];
    size_t p0 = (size_t)g_off[e0] + g_tslot[2*t];
    size_t p1 = (size_t)g_off[e1] + g_tslot[2*t+1];
    float w0 = g_tw[2*t], w1 = g_tw[2*t+1];
    float4 y0 = *(const float4*)(g_y + p0 * HIDDEN + 4*c);
    float4 y1 = *(const float4*)(g_y + p1 * HIDDEN + 4*c);
    float4 r;
    r.x = w0*y0.x + w1*y1.x; r.y = w0*y0.y + w1*y1.y;
    r.z = w0*y0.z + w1*y1.z; r.w = w0*y0.w + w1*y1.w;
    *(float4*)(out + (size_t)t * HIDDEN + 4*c) = r;
}

// ---------------- launcher ----------------
extern "C" void kernel_launch(void* const* d_in, const int* in_sizes, int n_in,
                              void* d_out, int out_size) {
    const float* X   = (const float*)d_in[0];
    const float* Wg  = (const float*)d_in[1];
    const float* Wgp = (const float*)d_in[2];
    const float* Wup = (const float*)d_in[3];
    const float* Wdp = (const float*)d_in[4];
    float* out = (float*)d_out;

    // smem: fused stage = (9216 + 2*4352) w = 17920 w = 71680 B; x2 = 143360
    //       down  stage = (9216 + 4352)  w = 13568 w = 54272 B; x2 = 108544
    const int SMEM_F = 2 * (9216 + 2 * 4352) * 4;
    const int SMEM_D = 2 * (9216 + 1 * 4352) * 4;
    cudaFuncSetAttribute(moe_gemm_mma<1>, cudaFuncAttributeMaxDynamicSharedMemorySize, SMEM_F);
    cudaFuncSetAttribute(moe_gemm_mma<0>, cudaFuncAttributeMaxDynamicSharedMemorySize, SMEM_D);

    zero_cnt_kernel<<<1, 32>>>();
    router_logits_kernel<<<(TOKENS * EXPERTS) / 256, 256>>>(X, Wg);
    router_topk_kernel<<<(TOKENS + 255) / 256, 256>>>();
    offsets_kernel<<<1, 1>>>();

    dim3 grid_f(TOKENS / 128, INTER / 128, EXPERTS);   // (16, 11, 16)
    moe_gemm_mma<1><<<grid_f, 256, SMEM_F>>>(X, Wgp, Wup);

    dim3 grid_d(TOKENS / 128, HIDDEN / 128, EXPERTS);  // (16, 16, 16)
    moe_gemm_mma<0><<<grid_d, 256, SMEM_D>>>(nullptr, Wdp, nullptr);

    combine_kernel<<<(TOKENS * (HIDDEN / 4)) / 256, 256>>>(out);
}

// round 5
// speedup vs baseline: 1.8696x; 1.0747x over previous
#include <cuda_runtime.h>
#include <cuda_bf16.h>
#include <cstdint>
#include <math.h>

#define TOKENS  2048
#define HIDDEN  2048
#define INTER   1408
#define EXPERTS 16
#define MAXPAIRS (TOKENS*2)

// ---------------- scratch ----------------
__device__ int   g_cnt[EXPERTS];
__device__ int   g_off[EXPERTS + 1];
__device__ int   g_tok[EXPERTS * TOKENS];
__device__ int   g_te[MAXPAIRS];
__device__ int   g_tslot[MAXPAIRS];
__device__ float g_tw[MAXPAIRS];
__device__ float g_logits[TOKENS * EXPERTS];
__device__ float g_gate[(size_t)MAXPAIRS * INTER];   // h = silu(g)*u
__device__ float g_y[(size_t)MAXPAIRS * HIDDEN];

// ---------------- helpers ----------------
__device__ __forceinline__ float sigmoidf_fast(float x) { return 1.0f / (1.0f + __expf(-x)); }

__device__ __forceinline__ uint32_t smem_u32(const void* p) {
    uint32_t a;
    asm("{ .reg .u64 t; cvta.to.shared.u64 t, %1; cvt.u32.u64 %0, t; }" : "=r"(a) : "l"(p));
    return a;
}

// split x,y into bf16 hi (packed) and bf16 lo (packed); lo = bf16(x - float(hi))
__device__ __forceinline__ void split2(float x, float y, uint32_t& hi, uint32_t& lo) {
    __nv_bfloat16 xh = __float2bfloat16_rn(x);
    __nv_bfloat16 yh = __float2bfloat16_rn(y);
    __nv_bfloat16 xl = __float2bfloat16_rn(x - __bfloat162float(xh));
    __nv_bfloat16 yl = __float2bfloat16_rn(y - __bfloat162float(yh));
    hi = ((uint32_t)__bfloat16_as_ushort(yh) << 16) | (uint32_t)__bfloat16_as_ushort(xh);
    lo = ((uint32_t)__bfloat16_as_ushort(yl) << 16) | (uint32_t)__bfloat16_as_ushort(xl);
}

// m16n8k16 bf16 MMA, fp32 accum
__device__ __forceinline__ void mma16(float* d, const uint32_t* a, const uint32_t* b) {
    asm volatile("mma.sync.aligned.m16n8k16.row.col.f32.bf16.bf16.f32 "
        "{%0,%1,%2,%3}, {%4,%5,%6,%7}, {%8,%9}, {%0,%1,%2,%3};"
        : "+f"(d[0]), "+f"(d[1]), "+f"(d[2]), "+f"(d[3])
        : "r"(a[0]), "r"(a[1]), "r"(a[2]), "r"(a[3]), "r"(b[0]), "r"(b[1]));
}

#define LDSM4(r0,r1,r2,r3,addr) \
    asm volatile("ldmatrix.sync.aligned.m8n8.x4.shared.b16 {%0,%1,%2,%3}, [%4];" \
        : "=r"(r0), "=r"(r1), "=r"(r2), "=r"(r3) : "r"(addr))
#define LDSM4T(r0,r1,r2,r3,addr) \
    asm volatile("ldmatrix.sync.aligned.m8n8.x4.trans.shared.b16 {%0,%1,%2,%3}, [%4];" \
        : "=r"(r0), "=r"(r1), "=r"(r2), "=r"(r3) : "r"(addr))

// ---------------- routing (proven) ----------------
__global__ void zero_cnt_kernel() { if (threadIdx.x < EXPERTS) g_cnt[threadIdx.x] = 0; }

__global__ void router_logits_kernel(const float* __restrict__ X, const float* __restrict__ Wg) {
    int idx = blockIdx.x * blockDim.x + threadIdx.x;
    int t = idx >> 4, e = idx & 15;
    const float* xr = X + (size_t)t * HIDDEN;
    float s0 = 0.f, s1 = 0.f, s2 = 0.f, s3 = 0.f;
    #pragma unroll 4
    for (int k = 0; k < HIDDEN; k += 4) {
        s0 = fmaf(xr[k+0], Wg[(k+0)*EXPERTS + e], s0);
        s1 = fmaf(xr[k+1], Wg[(k+1)*EXPERTS + e], s1);
        s2 = fmaf(xr[k+2], Wg[(k+2)*EXPERTS + e], s2);
        s3 = fmaf(xr[k+3], Wg[(k+3)*EXPERTS + e], s3);
    }
    g_logits[idx] = (s0 + s1) + (s2 + s3);
}

__global__ void router_topk_kernel() {
    int t = blockIdx.x * blockDim.x + threadIdx.x;
    if (t >= TOKENS) return;
    float l[EXPERTS];
    #pragma unroll
    for (int e = 0; e < EXPERTS; e++) l[e] = g_logits[t * EXPERTS + e];
    int e1 = 0; float v1 = l[0];
    #pragma unroll
    for (int e = 1; e < EXPERTS; e++) if (l[e] > v1) { v1 = l[e]; e1 = e; }
    int e2 = -1; float v2 = -3.4e38f;
    #pragma unroll
    for (int e = 0; e < EXPERTS; e++) { if (e == e1) continue; if (l[e] > v2) { v2 = l[e]; e2 = e; } }
    float w1 = sigmoidf_fast(v1), w2 = sigmoidf_fast(v2);
    float inv = 1.0f / (w1 + w2); w1 *= inv; w2 *= inv;
    int s1 = atomicAdd(&g_cnt[e1], 1);
    int s2 = atomicAdd(&g_cnt[e2], 1);
    g_tok[e1 * TOKENS + s1] = t;
    g_tok[e2 * TOKENS + s2] = t;
    g_te[2*t+0] = e1; g_tslot[2*t+0] = s1; g_tw[2*t+0] = w1;
    g_te[2*t+1] = e2; g_tslot[2*t+1] = s2; g_tw[2*t+1] = w2;
}

__global__ void offsets_kernel() {
    if (threadIdx.x == 0 && blockIdx.x == 0) {
        int a = 0;
        for (int e = 0; e < EXPERTS; e++) { g_off[e] = a; a += g_cnt[e]; }
        g_off[EXPERTS] = a;
    }
}

// ---------------- bf16 3-term mma.sync grouped GEMM ----------------
// FUSED=1: A = gathered X rows; B0=w_gate_proj, B1=w_up_proj; epi h=silu(g)*u -> g_gate
// FUSED=0: A = g_gate rows (h); B0=w_down_proj; epi raw -> g_y
// CTA tile 128x128, BK=32, warps 2(m)x4(n), warp tile 64x32.
template <int FUSED>
__global__ __launch_bounds__(256, 1)
void moe_gemm_bf16(const float* __restrict__ X,
                   const float* __restrict__ W0g,
                   const float* __restrict__ W1g) {
    constexpr int Kdim = FUSED ? HIDDEN : INTER;
    constexpr int Ndim = FUSED ? INTER : HIDDEN;
    constexpr int KT   = Kdim / 32;
    constexpr int SA   = 40;                     // A row stride (halves)
    constexpr int SB   = 136;                    // B k-row stride (halves)
    // offsets in halves within a stage
    constexpr int AH  = 0;
    constexpr int AL  = 128 * SA;                // 5120
    constexpr int B0H = 2 * 128 * SA;            // 10240
    constexpr int B0L = B0H + 32 * SB;           // 14592
    constexpr int B1H = B0L + 32 * SB;           // 18944
    constexpr int B1L = B1H + 32 * SB;           // 23296
    constexpr int STAGE_H = B0H + (FUSED ? 4 : 2) * 32 * SB;
    constexpr int STAGE_B = STAGE_H * 2;

    const int e  = blockIdx.z;
    const int ne = g_cnt[e];
    const int m0 = blockIdx.x * 128;
    if (m0 >= ne) return;
    const int n0  = blockIdx.y * 128;
    const int off = g_off[e];

    extern __shared__ __align__(16) uint16_t smh[];
    const uint32_t sbase = smem_u32(smh);

    const int tid  = threadIdx.x;
    const int lane = tid & 31;
    const int wid  = tid >> 5;
    const int wm   = wid & 1;
    const int wn   = wid >> 1;
    const int lg   = lane >> 2;
    const int lt   = lane & 3;
    const int q    = lane >> 3;      // ldmatrix matrix id
    const int rr   = lane & 7;       // ldmatrix row id

    // per-lane ldmatrix byte offsets (within stage, before AH/AL/B* bases)
    const uint32_t a_loff = (uint32_t)(((wm * 64 + (q & 1) * 8 + rr) * SA + (q >> 1) * 8) * 2);
    const uint32_t b_loff = (uint32_t)((rr * SB + wn * 32 + q * 8) * 2);

    // A gather: thread r=tid>>1, cols (tid&1)*16..+16
    const float* arow = nullptr;
    {
        int r = m0 + (tid >> 1);
        if (r < ne) arow = FUSED ? X + (size_t)g_tok[e * TOKENS + r] * HIDDEN
                                 : g_gate + (size_t)(off + r) * INTER;
    }
    const int acb  = (tid & 1) * 16;
    const int arsl = tid >> 1;
    // B loads: thread k=tid>>3, cols (tid&7)*16
    const int bk = tid >> 3;
    const int bn = (tid & 7) * 16;
    const float* w0 = W0g + (size_t)e * Kdim * Ndim + n0;
    const float* w1 = FUSED ? (W1g + (size_t)e * Kdim * Ndim + n0) : nullptr;

    float accG[4][4][4];
    float accU[FUSED ? 4 : 1][4][4];
    #pragma unroll
    for (int i = 0; i < 4; i++)
        #pragma unroll
        for (int j = 0; j < 4; j++)
            #pragma unroll
            for (int p = 0; p < 4; p++) { accG[i][j][p] = 0.f; if (FUSED) accU[i][j][p] = 0.f; }

    float4 av[4], b0v[4], b1v[4];

    auto load_tile = [&](int kt) {
        const int k0 = kt * 32;
        #pragma unroll
        for (int f = 0; f < 4; f++)
            av[f] = arow ? *(const float4*)(arow + k0 + acb + 4 * f) : make_float4(0,0,0,0);
        #pragma unroll
        for (int i = 0; i < 4; i++)
            b0v[i] = *(const float4*)(w0 + (size_t)(k0 + bk) * Ndim + bn + 4 * i);
        if (FUSED) {
            #pragma unroll
            for (int i = 0; i < 4; i++)
                b1v[i] = *(const float4*)(w1 + (size_t)(k0 + bk) * Ndim + bn + 4 * i);
        }
    };

    auto cvt8 = [](const float4& v0, const float4& v1, uint4& hi, uint4& lo) {
        split2(v0.x, v0.y, hi.x, lo.x);
        split2(v0.z, v0.w, hi.y, lo.y);
        split2(v1.x, v1.y, hi.z, lo.z);
        split2(v1.z, v1.w, hi.w, lo.w);
    };

    auto sts_tile = [&](int buf) {
        uint16_t* sp = smh + buf * STAGE_H;
        uint4 hi, lo;
        // A: two 8-col chunks
        cvt8(av[0], av[1], hi, lo);
        *(uint4*)(sp + AH + arsl * SA + acb)     = hi;
        *(uint4*)(sp + AL + arsl * SA + acb)     = lo;
        cvt8(av[2], av[3], hi, lo);
        *(uint4*)(sp + AH + arsl * SA + acb + 8) = hi;
        *(uint4*)(sp + AL + arsl * SA + acb + 8) = lo;
        // B0
        cvt8(b0v[0], b0v[1], hi, lo);
        *(uint4*)(sp + B0H + bk * SB + bn)     = hi;
        *(uint4*)(sp + B0L + bk * SB + bn)     = lo;
        cvt8(b0v[2], b0v[3], hi, lo);
        *(uint4*)(sp + B0H + bk * SB + bn + 8) = hi;
        *(uint4*)(sp + B0L + bk * SB + bn + 8) = lo;
        if (FUSED) {
            cvt8(b1v[0], b1v[1], hi, lo);
            *(uint4*)(sp + B1H + bk * SB + bn)     = hi;
            *(uint4*)(sp + B1L + bk * SB + bn)     = lo;
            cvt8(b1v[2], b1v[3], hi, lo);
            *(uint4*)(sp + B1H + bk * SB + bn + 8) = hi;
            *(uint4*)(sp + B1L + bk * SB + bn + 8) = lo;
        }
    };

    load_tile(0);
    sts_tile(0);
    __syncthreads();

    for (int kt = 0; kt < KT; kt++) {
        const uint32_t st = sbase + (uint32_t)((kt & 1) * STAGE_B);
        if (kt + 1 < KT) load_tile(kt + 1);

        #pragma unroll
        for (int ks = 0; ks < 2; ks++) {
            const uint32_t bks = (uint32_t)(ks * 16 * SB * 2);
            uint32_t bGh[4][2], bGl[4][2];
            uint32_t bUh[FUSED ? 4 : 1][2], bUl[FUSED ? 4 : 1][2];
            {
                uint32_t t0, t1, t2, t3;
                uint32_t ba = st + (uint32_t)(B0H * 2) + b_loff + bks;
                LDSM4T(t0, t1, t2, t3, ba);
                bGh[0][0]=t0; bGh[1][0]=t1; bGh[2][0]=t2; bGh[3][0]=t3;
                LDSM4T(t0, t1, t2, t3, ba + 8 * SB * 2);
                bGh[0][1]=t0; bGh[1][1]=t1; bGh[2][1]=t2; bGh[3][1]=t3;
                ba = st + (uint32_t)(B0L * 2) + b_loff + bks;
                LDSM4T(t0, t1, t2, t3, ba);
                bGl[0][0]=t0; bGl[1][0]=t1; bGl[2][0]=t2; bGl[3][0]=t3;
                LDSM4T(t0, t1, t2, t3, ba + 8 * SB * 2);
                bGl[0][1]=t0; bGl[1][1]=t1; bGl[2][1]=t2; bGl[3][1]=t3;
                if (FUSED) {
                    ba = st + (uint32_t)(B1H * 2) + b_loff + bks;
                    LDSM4T(t0, t1, t2, t3, ba);
                    bUh[0][0]=t0; bUh[1][0]=t1; bUh[2][0]=t2; bUh[3][0]=t3;
                    LDSM4T(t0, t1, t2, t3, ba + 8 * SB * 2);
                    bUh[0][1]=t0; bUh[1][1]=t1; bUh[2][1]=t2; bUh[3][1]=t3;
                    ba = st + (uint32_t)(B1L * 2) + b_loff + bks;
                    LDSM4T(t0, t1, t2, t3, ba);
                    bUl[0][0]=t0; bUl[1][0]=t1; bUl[2][0]=t2; bUl[3][0]=t3;
                    LDSM4T(t0, t1, t2, t3, ba + 8 * SB * 2);
                    bUl[0][1]=t0; bUl[1][1]=t1; bUl[2][1]=t2; bUl[3][1]=t3;
                }
            }
            #pragma unroll
            for (int mf = 0; mf < 4; mf++) {
                uint32_t ah[4], al[4];
                const uint32_t aa = st + a_loff + (uint32_t)(mf * 16 * SA * 2) + (uint32_t)(ks * 32);
                LDSM4(ah[0], ah[1], ah[2], ah[3], aa + (uint32_t)(AH * 2));
                LDSM4(al[0], al[1], al[2], al[3], aa + (uint32_t)(AL * 2));
                #pragma unroll
                for (int nf = 0; nf < 4; nf++) {
                    mma16(accG[mf][nf], ah, bGh[nf]);
                    mma16(accG[mf][nf], al, bGh[nf]);
                    mma16(accG[mf][nf], ah, bGl[nf]);
                    if (FUSED) {
                        mma16(accU[mf][nf], ah, bUh[nf]);
                        mma16(accU[mf][nf], al, bUh[nf]);
                        mma16(accU[mf][nf], ah, bUl[nf]);
                    }
                }
            }
        }
        if (kt + 1 < KT) {
            sts_tile((kt + 1) & 1);
            __syncthreads();
        }
    }

    // ---- epilogue ----
    #pragma unroll
    for (int mf = 0; mf < 4; mf++) {
        #pragma unroll
        for (int h = 0; h < 2; h++) {
            int r = m0 + wm * 64 + mf * 16 + lg + h * 8;
            if (r >= ne) continue;
            if (FUSED) {
                float* orow = g_gate + (size_t)(off + r) * INTER + n0 + wn * 32 + lt * 2;
                #pragma unroll
                for (int nf = 0; nf < 4; nf++) {
                    float g0 = accG[mf][nf][2*h],   g1 = accG[mf][nf][2*h+1];
                    float u0 = accU[mf][nf][2*h],   u1 = accU[mf][nf][2*h+1];
                    float2 v;
                    v.x = g0 * sigmoidf_fast(g0) * u0;
                    v.y = g1 * sigmoidf_fast(g1) * u1;
                    *(float2*)(orow + nf * 8) = v;
                }
            } else {
                float* orow = g_y + (size_t)(off + r) * HIDDEN + n0 + wn * 32 + lt * 2;
                #pragma unroll
                for (int nf = 0; nf < 4; nf++) {
                    float2 v = make_float2(accG[mf][nf][2*h], accG[mf][nf][2*h+1]);
                    *(float2*)(orow + nf * 8) = v;
                }
            }
        }
    }
}

// ---------------- combine ----------------
__global__ void combine_kernel(float* __restrict__ out) {
    int idx = blockIdx.x * blockDim.x + threadIdx.x;
    int t = idx / (HIDDEN / 4);
    int c = idx % (HIDDEN / 4);
    int e0 = g_te[2*t], e1 = g_te[2*t+1];
    size_t p0 = (size_t)g_off[e0] + g_tslot[2*t];
    size_t p1 = (size_t)g_off[e1] + g_tslot[2*t+1];
    float w0 = g_tw[2*t], w1 = g_tw[2*t+1];
    float4 y0 = *(const float4*)(g_y + p0 * HIDDEN + 4*c);
    float4 y1 = *(const float4*)(g_y + p1 * HIDDEN + 4*c);
    float4 r;
    r.x = w0*y0.x + w1*y1.x; r.y = w0*y0.y + w1*y1.y;
    r.z = w0*y0.z + w1*y1.z; r.w = w0*y0.w + w1*y1.w;
    *(float4*)(out + (size_t)t * HIDDEN + 4*c) = r;
}

// ---------------- launcher ----------------
extern "C" void kernel_launch(void* const* d_in, const int* in_sizes, int n_in,
                              void* d_out, int out_size) {
    const float* X   = (const float*)d_in[0];
    const float* Wg  = (const float*)d_in[1];
    const float* Wgp = (const float*)d_in[2];
    const float* Wup = (const float*)d_in[3];
    const float* Wdp = (const float*)d_in[4];
    float* out = (float*)d_out;

    // smem: fused stage = (10240 + 4*4352)*2 = 55296 B, x2 = 110592
    //       down  stage = (10240 + 2*4352)*2 = 37888 B, x2 = 75776
    const int SMEM_F = 2 * (10240 + 4 * 4352) * 2;
    const int SMEM_D = 2 * (10240 + 2 * 4352) * 2;
    cudaFuncSetAttribute(moe_gemm_bf16<1>, cudaFuncAttributeMaxDynamicSharedMemorySize, SMEM_F);
    cudaFuncSetAttribute(moe_gemm_bf16<0>, cudaFuncAttributeMaxDynamicSharedMemorySize, SMEM_D);

    zero_cnt_kernel<<<1, 32>>>();
    router_logits_kernel<<<(TOKENS * EXPERTS) / 256, 256>>>(X, Wg);
    router_topk_kernel<<<(TOKENS + 255) / 256, 256>>>();
    offsets_kernel<<<1, 1>>>();

    dim3 grid_f(TOKENS / 128, INTER / 128, EXPERTS);   // (16, 11, 16)
    moe_gemm_bf16<1><<<grid_f, 256, SMEM_F>>>(X, Wgp, Wup);

    dim3 grid_d(TOKENS / 128, HIDDEN / 128, EXPERTS);  // (16, 16, 16)
    moe_gemm_bf16<0><<<grid_d, 256, SMEM_D>>>(nullptr, Wdp, nullptr);

    combine_kernel<<<(TOKENS * (HIDDEN / 4)) / 256, 256>>>(out);
}

// round 6
// speedup vs baseline: 1.8916x; 1.0118x over previous
#include <cuda_runtime.h>
#include <cuda_bf16.h>
#include <cstdint>
#include <math.h>

#define TOKENS  2048
#define HIDDEN  2048
#define INTER   1408
#define EXPERTS 16
#define MAXPAIRS (TOKENS*2)

// ---------------- scratch ----------------
__device__ int   g_cnt[EXPERTS];
__device__ int   g_off[EXPERTS + 1];
__device__ int   g_tok[EXPERTS * TOKENS];
__device__ int   g_te[MAXPAIRS];
__device__ int   g_tslot[MAXPAIRS];
__device__ float g_tw[MAXPAIRS];
__device__ float g_logits[TOKENS * EXPERTS];
__device__ float g_y[(size_t)MAXPAIRS * HIDDEN];

// pre-split bf16 operands
__device__ __nv_bfloat16 c_Xh[(size_t)TOKENS * HIDDEN];
__device__ __nv_bfloat16 c_Xl[(size_t)TOKENS * HIDDEN];
__device__ __nv_bfloat16 c_W0h[(size_t)EXPERTS * HIDDEN * INTER];
__device__ __nv_bfloat16 c_W0l[(size_t)EXPERTS * HIDDEN * INTER];
__device__ __nv_bfloat16 c_W1h[(size_t)EXPERTS * HIDDEN * INTER];
__device__ __nv_bfloat16 c_W1l[(size_t)EXPERTS * HIDDEN * INTER];
__device__ __nv_bfloat16 c_Wdh[(size_t)EXPERTS * INTER * HIDDEN];
__device__ __nv_bfloat16 c_Wdl[(size_t)EXPERTS * INTER * HIDDEN];
__device__ __nv_bfloat16 g_hh[(size_t)(MAXPAIRS + 128) * INTER];
__device__ __nv_bfloat16 g_hl[(size_t)(MAXPAIRS + 128) * INTER];

// ---------------- helpers ----------------
__device__ __forceinline__ float sigmoidf_fast(float x) { return 1.0f / (1.0f + __expf(-x)); }

__device__ __forceinline__ uint32_t smem_u32(const void* p) {
    uint32_t a;
    asm("{ .reg .u64 t; cvta.to.shared.u64 t, %1; cvt.u32.u64 %0, t; }" : "=r"(a) : "l"(p));
    return a;
}
__device__ __forceinline__ void split2(float x, float y, uint32_t& hi, uint32_t& lo) {
    __nv_bfloat16 xh = __float2bfloat16_rn(x);
    __nv_bfloat16 yh = __float2bfloat16_rn(y);
    __nv_bfloat16 xl = __float2bfloat16_rn(x - __bfloat162float(xh));
    __nv_bfloat16 yl = __float2bfloat16_rn(y - __bfloat162float(yh));
    hi = ((uint32_t)__bfloat16_as_ushort(yh) << 16) | (uint32_t)__bfloat16_as_ushort(xh);
    lo = ((uint32_t)__bfloat16_as_ushort(yl) << 16) | (uint32_t)__bfloat16_as_ushort(xl);
}
__device__ __forceinline__ void mma16(float* d, const uint32_t* a, const uint32_t* b) {
    asm volatile("mma.sync.aligned.m16n8k16.row.col.f32.bf16.bf16.f32 "
        "{%0,%1,%2,%3}, {%4,%5,%6,%7}, {%8,%9}, {%0,%1,%2,%3};"
        : "+f"(d[0]), "+f"(d[1]), "+f"(d[2]), "+f"(d[3])
        : "r"(a[0]), "r"(a[1]), "r"(a[2]), "r"(a[3]), "r"(b[0]), "r"(b[1]));
}
#define LDSM4(r0,r1,r2,r3,addr) \
    asm volatile("ldmatrix.sync.aligned.m8n8.x4.shared.b16 {%0,%1,%2,%3}, [%4];" \
        : "=r"(r0), "=r"(r1), "=r"(r2), "=r"(r3) : "r"(addr))
#define LDSM4T(r0,r1,r2,r3,addr) \
    asm volatile("ldmatrix.sync.aligned.m8n8.x4.trans.shared.b16 {%0,%1,%2,%3}, [%4];" \
        : "=r"(r0), "=r"(r1), "=r"(r2), "=r"(r3) : "r"(addr))
#define CP16(dst, src, sz) \
    asm volatile("cp.async.cg.shared.global [%0], [%1], 16, %2;" \
        :: "r"(dst), "l"(src), "r"(sz) : "memory")
#define CP_COMMIT() asm volatile("cp.async.commit_group;" ::: "memory")
#define CP_WAIT1()  asm volatile("cp.async.wait_group 1;" ::: "memory")

// ---------------- split (fp32 -> bf16 hi + lo) ----------------
__global__ void split_kernel(const float* __restrict__ src,
                             __nv_bfloat16* __restrict__ hi,
                             __nv_bfloat16* __restrict__ lo, int n8) {
    int i = blockIdx.x * blockDim.x + threadIdx.x;
    if (i >= n8) return;
    const float4* s = (const float4*)src + 2 * (size_t)i;
    float4 v0 = s[0], v1 = s[1];
    uint32_t h0,h1,h2,h3,l0,l1,l2,l3;
    split2(v0.x, v0.y, h0, l0); split2(v0.z, v0.w, h1, l1);
    split2(v1.x, v1.y, h2, l2); split2(v1.z, v1.w, h3, l3);
    *(uint4*)(hi + 8 * (size_t)i) = make_uint4(h0, h1, h2, h3);
    *(uint4*)(lo + 8 * (size_t)i) = make_uint4(l0, l1, l2, l3);
}

// ---------------- routing (proven) ----------------
__global__ void zero_cnt_kernel() { if (threadIdx.x < EXPERTS) g_cnt[threadIdx.x] = 0; }

__global__ void router_logits_kernel(const float* __restrict__ X, const float* __restrict__ Wg) {
    int idx = blockIdx.x * blockDim.x + threadIdx.x;
    int t = idx >> 4, e = idx & 15;
    const float* xr = X + (size_t)t * HIDDEN;
    float s0 = 0.f, s1 = 0.f, s2 = 0.f, s3 = 0.f;
    #pragma unroll 4
    for (int k = 0; k < HIDDEN; k += 4) {
        s0 = fmaf(xr[k+0], Wg[(k+0)*EXPERTS + e], s0);
        s1 = fmaf(xr[k+1], Wg[(k+1)*EXPERTS + e], s1);
        s2 = fmaf(xr[k+2], Wg[(k+2)*EXPERTS + e], s2);
        s3 = fmaf(xr[k+3], Wg[(k+3)*EXPERTS + e], s3);
    }
    g_logits[idx] = (s0 + s1) + (s2 + s3);
}

__global__ void router_topk_kernel() {
    int t = blockIdx.x * blockDim.x + threadIdx.x;
    if (t >= TOKENS) return;
    float l[EXPERTS];
    #pragma unroll
    for (int e = 0; e < EXPERTS; e++) l[e] = g_logits[t * EXPERTS + e];
    int e1 = 0; float v1 = l[0];
    #pragma unroll
    for (int e = 1; e < EXPERTS; e++) if (l[e] > v1) { v1 = l[e]; e1 = e; }
    int e2 = -1; float v2 = -3.4e38f;
    #pragma unroll
    for (int e = 0; e < EXPERTS; e++) { if (e == e1) continue; if (l[e] > v2) { v2 = l[e]; e2 = e; } }
    float w1 = sigmoidf_fast(v1), w2 = sigmoidf_fast(v2);
    float inv = 1.0f / (w1 + w2); w1 *= inv; w2 *= inv;
    int s1 = atomicAdd(&g_cnt[e1], 1);
    int s2 = atomicAdd(&g_cnt[e2], 1);
    g_tok[e1 * TOKENS + s1] = t;
    g_tok[e2 * TOKENS + s2] = t;
    g_te[2*t+0] = e1; g_tslot[2*t+0] = s1; g_tw[2*t+0] = w1;
    g_te[2*t+1] = e2; g_tslot[2*t+1] = s2; g_tw[2*t+1] = w2;
}

__global__ void offsets_kernel() {
    if (threadIdx.x == 0 && blockIdx.x == 0) {
        int a = 0;
        for (int e = 0; e < EXPERTS; e++) { g_off[e] = a; a += g_cnt[e]; }
        g_off[EXPERTS] = a;
    }
}

// ---------------- bf16 3-term mma.sync grouped GEMM, cp.async 3-stage ----------------
// FUSED=1: A = gathered Xh/Xl rows; B0=W0(gate), B1=W1(up); epi h=silu(g)*u -> g_hh/g_hl
// FUSED=0: A = g_hh/g_hl rows;      B0=Wd;               epi raw -> g_y
template <int FUSED>
__global__ __launch_bounds__(256, 1)
void moe_gemm_bf16(const __nv_bfloat16* __restrict__ Agh,
                   const __nv_bfloat16* __restrict__ Agl,
                   const __nv_bfloat16* __restrict__ B0h_g,
                   const __nv_bfloat16* __restrict__ B0l_g,
                   const __nv_bfloat16* __restrict__ B1h_g,
                   const __nv_bfloat16* __restrict__ B1l_g) {
    constexpr int Kdim = FUSED ? HIDDEN : INTER;
    constexpr int Ndim = FUSED ? INTER : HIDDEN;
    constexpr int KT   = Kdim / 32;
    constexpr int SA   = 40;   // halves
    constexpr int SB   = 136;  // halves
    constexpr int AH  = 0;
    constexpr int AL  = 128 * SA;          // 5120
    constexpr int B0H = 2 * 128 * SA;      // 10240
    constexpr int B0L = B0H + 32 * SB;
    constexpr int B1H = B0L + 32 * SB;
    constexpr int B1L = B1H + 32 * SB;
    constexpr int STAGE_H = B0H + (FUSED ? 4 : 2) * 32 * SB;
    constexpr int STAGE_B = STAGE_H * 2;

    const int e  = blockIdx.z;
    const int ne = g_cnt[e];
    const int m0 = blockIdx.x * 128;
    if (m0 >= ne) return;
    const int n0  = blockIdx.y * 128;
    const int off = g_off[e];

    extern __shared__ __align__(16) uint16_t smh[];
    const uint32_t sbase = smem_u32(smh);

    const int tid  = threadIdx.x;
    const int lane = tid & 31;
    const int wid  = tid >> 5;
    const int wm   = wid & 1;
    const int wn   = wid >> 1;
    const int lg   = lane >> 2;
    const int lt   = lane & 3;
    const int q    = lane >> 3;
    const int rr   = lane & 7;

    const uint32_t a_loff = (uint32_t)(((wm * 64 + (q & 1) * 8 + rr) * SA + (q >> 1) * 8) * 2);
    const uint32_t b_loff = (uint32_t)((rr * SB + wn * 32 + q * 8) * 2);

    // ---- cp.async source/dest setup ----
    // A: thread covers row (tid>>1), halves [(tid&1)*16, +16) => 2 chunks
    const int ar  = tid >> 1;
    const int ach = (tid & 1) * 16;
    const __nv_bfloat16 *pAh, *pAl;
    uint32_t aSz;
    {
        int r = m0 + ar;
        if (FUSED) {
            if (r < ne) {
                size_t rb = (size_t)g_tok[e * TOKENS + r] * Kdim + ach;
                pAh = Agh + rb; pAl = Agl + rb; aSz = 16;
            } else { pAh = Agh; pAl = Agl; aSz = 0; }
        } else {
            size_t rb = (size_t)(off + r) * Kdim + ach;
            pAh = Agh + rb; pAl = Agl + rb; aSz = 16;
        }
    }
    const uint32_t dA = (uint32_t)((ar * SA + ach) * 2);
    // B: thread covers k-row (tid>>3), halves [(tid&7)*16, +16) => 2 chunks
    const int br  = tid >> 3;
    const int bch = (tid & 7) * 16;
    const size_t bstart = (size_t)e * Kdim * Ndim + (size_t)br * Ndim + n0 + bch;
    const __nv_bfloat16* pB0h = B0h_g + bstart;
    const __nv_bfloat16* pB0l = B0l_g + bstart;
    const __nv_bfloat16* pB1h = FUSED ? (B1h_g + bstart) : nullptr;
    const __nv_bfloat16* pB1l = FUSED ? (B1l_g + bstart) : nullptr;
    const uint32_t dB = (uint32_t)((br * SB + bch) * 2);

    auto issue = [&](int kt, int buf) {
        const uint32_t st = sbase + (uint32_t)buf * STAGE_B;
        const size_t ak = (size_t)kt * 32;
        const size_t bk = (size_t)kt * 32 * Ndim;
        CP16(st + dA,                 pAh + ak,      aSz);
        CP16(st + dA + 16,            pAh + ak + 8,  aSz);
        CP16(st + dA + AL * 2,        pAl + ak,      aSz);
        CP16(st + dA + AL * 2 + 16,   pAl + ak + 8,  aSz);
        CP16(st + dB + B0H * 2,       pB0h + bk,     16u);
        CP16(st + dB + B0H * 2 + 16,  pB0h + bk + 8, 16u);
        CP16(st + dB + B0L * 2,       pB0l + bk,     16u);
        CP16(st + dB + B0L * 2 + 16,  pB0l + bk + 8, 16u);
        if (FUSED) {
            CP16(st + dB + B1H * 2,       pB1h + bk,     16u);
            CP16(st + dB + B1H * 2 + 16,  pB1h + bk + 8, 16u);
            CP16(st + dB + B1L * 2,       pB1l + bk,     16u);
            CP16(st + dB + B1L * 2 + 16,  pB1l + bk + 8, 16u);
        }
    };

    float accG[4][4][4];
    float accU[FUSED ? 4 : 1][4][4];
    #pragma unroll
    for (int i = 0; i < 4; i++)
        #pragma unroll
        for (int j = 0; j < 4; j++)
            #pragma unroll
            for (int p = 0; p < 4; p++) { accG[i][j][p] = 0.f; if (FUSED) accU[i][j][p] = 0.f; }

    // prologue: stages 0,1
    issue(0, 0); CP_COMMIT();
    if (KT > 1) issue(1, 1);
    CP_COMMIT();
    CP_WAIT1();
    __syncthreads();

    for (int kt = 0; kt < KT; kt++) {
        if (kt + 2 < KT) issue(kt + 2, (kt + 2) % 3);
        CP_COMMIT();

        const uint32_t st = sbase + (uint32_t)(kt % 3) * STAGE_B;
        #pragma unroll
        for (int ks = 0; ks < 2; ks++) {
            const uint32_t bks = (uint32_t)(ks * 16 * SB * 2);
            uint32_t bGh[4][2], bGl[4][2];
            uint32_t bUh[FUSED ? 4 : 1][2], bUl[FUSED ? 4 : 1][2];
            {
                uint32_t t0, t1, t2, t3;
                uint32_t ba = st + (uint32_t)(B0H * 2) + b_loff + bks;
                LDSM4T(t0, t1, t2, t3, ba);
                bGh[0][0]=t0; bGh[1][0]=t1; bGh[2][0]=t2; bGh[3][0]=t3;
                LDSM4T(t0, t1, t2, t3, ba + 8 * SB * 2);
                bGh[0][1]=t0; bGh[1][1]=t1; bGh[2][1]=t2; bGh[3][1]=t3;
                ba = st + (uint32_t)(B0L * 2) + b_loff + bks;
                LDSM4T(t0, t1, t2, t3, ba);
                bGl[0][0]=t0; bGl[1][0]=t1; bGl[2][0]=t2; bGl[3][0]=t3;
                LDSM4T(t0, t1, t2, t3, ba + 8 * SB * 2);
                bGl[0][1]=t0; bGl[1][1]=t1; bGl[2][1]=t2; bGl[3][1]=t3;
                if (FUSED) {
                    ba = st + (uint32_t)(B1H * 2) + b_loff + bks;
                    LDSM4T(t0, t1, t2, t3, ba);
                    bUh[0][0]=t0; bUh[1][0]=t1; bUh[2][0]=t2; bUh[3][0]=t3;
                    LDSM4T(t0, t1, t2, t3, ba + 8 * SB * 2);
                    bUh[0][1]=t0; bUh[1][1]=t1; bUh[2][1]=t2; bUh[3][1]=t3;
                    ba = st + (uint32_t)(B1L * 2) + b_loff + bks;
                    LDSM4T(t0, t1, t2, t3, ba);
                    bUl[0][0]=t0; bUl[1][0]=t1; bUl[2][0]=t2; bUl[3][0]=t3;
                    LDSM4T(t0, t1, t2, t3, ba + 8 * SB * 2);
                    bUl[0][1]=t0; bUl[1][1]=t1; bUl[2][1]=t2; bUl[3][1]=t3;
                }
            }
            #pragma unroll
            for (int mf = 0; mf < 4; mf++) {
                uint32_t ah[4], al[4];
                const uint32_t aa = st + a_loff + (uint32_t)(mf * 16 * SA * 2) + (uint32_t)(ks * 32);
                LDSM4(ah[0], ah[1], ah[2], ah[3], aa + (uint32_t)(AH * 2));
                LDSM4(al[0], al[1], al[2], al[3], aa + (uint32_t)(AL * 2));
                #pragma unroll
                for (int nf = 0; nf < 4; nf++) {
                    mma16(accG[mf][nf], ah, bGh[nf]);
                    mma16(accG[mf][nf], al, bGh[nf]);
                    mma16(accG[mf][nf], ah, bGl[nf]);
                    if (FUSED) {
                        mma16(accU[mf][nf], ah, bUh[nf]);
                        mma16(accU[mf][nf], al, bUh[nf]);
                        mma16(accU[mf][nf], ah, bUl[nf]);
                    }
                }
            }
        }
        CP_WAIT1();
        __syncthreads();
    }

    // ---- epilogue ----
    #pragma unroll
    for (int mf = 0; mf < 4; mf++) {
        #pragma unroll
        for (int h = 0; h < 2; h++) {
            int r = m0 + wm * 64 + mf * 16 + lg + h * 8;
            if (r >= ne) continue;
            int col = n0 + wn * 32 + lt * 2;
            if (FUSED) {
                size_t base = (size_t)(off + r) * INTER + col;
                #pragma unroll
                for (int nf = 0; nf < 4; nf++) {
                    float g0 = accG[mf][nf][2*h],   g1 = accG[mf][nf][2*h+1];
                    float u0 = accU[mf][nf][2*h],   u1 = accU[mf][nf][2*h+1];
                    float h0 = g0 * sigmoidf_fast(g0) * u0;
                    float h1 = g1 * sigmoidf_fast(g1) * u1;
                    uint32_t hh, hl;
                    split2(h0, h1, hh, hl);
                    *(uint32_t*)(g_hh + base + nf * 8) = hh;
                    *(uint32_t*)(g_hl + base + nf * 8) = hl;
                }
            } else {
                float* orow = g_y + (size_t)(off + r) * HIDDEN + col;
                #pragma unroll
                for (int nf = 0; nf < 4; nf++) {
                    float2 v = make_float2(accG[mf][nf][2*h], accG[mf][nf][2*h+1]);
                    *(float2*)(orow + nf * 8) = v;
                }
            }
        }
    }
}

// ---------------- combine ----------------
__global__ void combine_kernel(float* __restrict__ out) {
    int idx = blockIdx.x * blockDim.x + threadIdx.x;
    int t = idx / (HIDDEN / 4);
    int c = idx % (HIDDEN / 4);
    int e0 = g_te[2*t], e1 = g_te[2*t+1];
    size_t p0 = (size_t)g_off[e0] + g_tslot[2*t];
    size_t p1 = (size_t)g_off[e1] + g_tslot[2*t+1];
    float w0 = g_tw[2*t], w1 = g_tw[2*t+1];
    float4 y0 = *(const float4*)(g_y + p0 * HIDDEN + 4*c);
    float4 y1 = *(const float4*)(g_y + p1 * HIDDEN + 4*c);
    float4 r;
    r.x = w0*y0.x + w1*y1.x; r.y = w0*y0.y + w1*y1.y;
    r.z = w0*y0.z + w1*y1.z; r.w = w0*y0.w + w1*y1.w;
    *(float4*)(out + (size_t)t * HIDDEN + 4*c) = r;
}

// ---------------- launcher ----------------
extern "C" void kernel_launch(void* const* d_in, const int* in_sizes, int n_in,
                              void* d_out, int out_size) {
    const float* X   = (const float*)d_in[0];
    const float* Wg  = (const float*)d_in[1];
    const float* Wgp = (const float*)d_in[2];
    const float* Wup = (const float*)d_in[3];
    const float* Wdp = (const float*)d_in[4];
    float* out = (float*)d_out;

    // device symbol addresses (host-side)
    __nv_bfloat16 *xh, *xl, *w0h, *w0l, *w1h, *w1l, *wdh, *wdl, *hh, *hl;
    cudaGetSymbolAddress((void**)&xh,  c_Xh);  cudaGetSymbolAddress((void**)&xl,  c_Xl);
    cudaGetSymbolAddress((void**)&w0h, c_W0h); cudaGetSymbolAddress((void**)&w0l, c_W0l);
    cudaGetSymbolAddress((void**)&w1h, c_W1h); cudaGetSymbolAddress((void**)&w1l, c_W1l);
    cudaGetSymbolAddress((void**)&wdh, c_Wdh); cudaGetSymbolAddress((void**)&wdl, c_Wdl);
    cudaGetSymbolAddress((void**)&hh,  g_hh);  cudaGetSymbolAddress((void**)&hl,  g_hl);

    constexpr int STAGE_F = (2*128*40 + 4*32*136) * 2;   // 55296 B
    constexpr int STAGE_D = (2*128*40 + 2*32*136) * 2;   // 37888 B
    const int SMEM_F = 3 * STAGE_F;                      // 165888
    const int SMEM_D = 3 * STAGE_D;                      // 113664
    cudaFuncSetAttribute(moe_gemm_bf16<1>, cudaFuncAttributeMaxDynamicSharedMemorySize, SMEM_F);
    cudaFuncSetAttribute(moe_gemm_bf16<0>, cudaFuncAttributeMaxDynamicSharedMemorySize, SMEM_D);

    // routing
    zero_cnt_kernel<<<1, 32>>>();
    router_logits_kernel<<<(TOKENS * EXPERTS) / 256, 256>>>(X, Wg);
    router_topk_kernel<<<(TOKENS + 255) / 256, 256>>>();
    offsets_kernel<<<1, 1>>>();

    // operand pre-split
    const int NX = TOKENS * HIDDEN / 8;
    const int NW = EXPERTS * HIDDEN * INTER / 8;
    split_kernel<<<(NX + 255) / 256, 256>>>(X,   xh,  xl,  NX);
    split_kernel<<<(NW + 255) / 256, 256>>>(Wgp, w0h, w0l, NW);
    split_kernel<<<(NW + 255) / 256, 256>>>(Wup, w1h, w1l, NW);
    split_kernel<<<(NW + 255) / 256, 256>>>(Wdp, wdh, wdl, NW);

    // fused gate+up GEMM + SwiGLU
    dim3 grid_f(TOKENS / 128, INTER / 128, EXPERTS);
    moe_gemm_bf16<1><<<grid_f, 256, SMEM_F>>>(xh, xl, w0h, w0l, w1h, w1l);

    // down GEMM
    dim3 grid_d(TOKENS / 128, HIDDEN / 128, EXPERTS);
    moe_gemm_bf16<0><<<grid_d, 256, SMEM_D>>>(hh, hl, wdh, wdl, nullptr, nullptr);

    combine_kernel<<<(TOKENS * (HIDDEN / 4)) / 256, 256>>>(out);
}

// round 7
// speedup vs baseline: 2.5619x; 1.3543x over previous
#include <cuda_runtime.h>
#include <cuda_fp16.h>
#include <cstdint>
#include <math.h>

#define TOKENS  2048
#define HIDDEN  2048
#define INTER   1408
#define EXPERTS 16
#define MAXPAIRS (TOKENS*2)

// ---------------- scratch ----------------
__device__ int   g_cnt[EXPERTS];
__device__ int   g_off[EXPERTS + 1];
__device__ int   g_tok[EXPERTS * TOKENS];
__device__ int   g_te[MAXPAIRS];
__device__ int   g_tslot[MAXPAIRS];
__device__ float g_tw[MAXPAIRS];
__device__ float g_logits[TOKENS * EXPERTS];
__device__ float g_y[(size_t)MAXPAIRS * HIDDEN];

// pre-split fp16 operands: A-side hi/lo, B-side hi only
__device__ __half c_Xh[(size_t)TOKENS * HIDDEN];
__device__ __half c_Xl[(size_t)TOKENS * HIDDEN];
__device__ __half c_W0h[(size_t)EXPERTS * HIDDEN * INTER];
__device__ __half c_W1h[(size_t)EXPERTS * HIDDEN * INTER];
__device__ __half c_Wdh[(size_t)EXPERTS * INTER * HIDDEN];
__device__ __half g_hh[(size_t)(MAXPAIRS + 128) * INTER];
__device__ __half g_hl[(size_t)(MAXPAIRS + 128) * INTER];

// ---------------- helpers ----------------
__device__ __forceinline__ float sigmoidf_fast(float x) { return 1.0f / (1.0f + __expf(-x)); }

__device__ __forceinline__ uint32_t smem_u32(const void* p) {
    uint32_t a;
    asm("{ .reg .u64 t; cvta.to.shared.u64 t, %1; cvt.u32.u64 %0, t; }" : "=r"(a) : "l"(p));
    return a;
}
// split x,y into packed fp16 hi and lo; lo = h(x - float(hi)) (exact to ~2^-22)
__device__ __forceinline__ void split2h(float x, float y, uint32_t& hi, uint32_t& lo) {
    __half xh = __float2half_rn(x);
    __half yh = __float2half_rn(y);
    __half xl = __float2half_rn(x - __half2float(xh));
    __half yl = __float2half_rn(y - __half2float(yh));
    hi = ((uint32_t)__half_as_ushort(yh) << 16) | (uint32_t)__half_as_ushort(xh);
    lo = ((uint32_t)__half_as_ushort(yl) << 16) | (uint32_t)__half_as_ushort(xl);
}
__device__ __forceinline__ uint32_t cvt2h(float x, float y) {
    __half2 h = __floats2half2_rn(x, y);
    return *(uint32_t*)&h;
}
// m16n8k16 fp16 MMA, fp32 accum
__device__ __forceinline__ void mma16(float* d, const uint32_t* a, const uint32_t* b) {
    asm volatile("mma.sync.aligned.m16n8k16.row.col.f32.f16.f16.f32 "
        "{%0,%1,%2,%3}, {%4,%5,%6,%7}, {%8,%9}, {%0,%1,%2,%3};"
        : "+f"(d[0]), "+f"(d[1]), "+f"(d[2]), "+f"(d[3])
        : "r"(a[0]), "r"(a[1]), "r"(a[2]), "r"(a[3]), "r"(b[0]), "r"(b[1]));
}
#define LDSM4(r0,r1,r2,r3,addr) \
    asm volatile("ldmatrix.sync.aligned.m8n8.x4.shared.b16 {%0,%1,%2,%3}, [%4];" \
        : "=r"(r0), "=r"(r1), "=r"(r2), "=r"(r3) : "r"(addr))
#define LDSM4T(r0,r1,r2,r3,addr) \
    asm volatile("ldmatrix.sync.aligned.m8n8.x4.trans.shared.b16 {%0,%1,%2,%3}, [%4];" \
        : "=r"(r0), "=r"(r1), "=r"(r2), "=r"(r3) : "r"(addr))
#define CP16(dst, src, sz) \
    asm volatile("cp.async.cg.shared.global [%0], [%1], 16, %2;" \
        :: "r"(dst), "l"(src), "r"(sz) : "memory")
#define CP_COMMIT() asm volatile("cp.async.commit_group;" ::: "memory")
#define CP_WAIT1()  asm volatile("cp.async.wait_group 1;" ::: "memory")

// ---------------- conversion kernels ----------------
// A-side: fp32 -> fp16 hi + lo
__global__ void split_kernel(const float* __restrict__ src,
                             __half* __restrict__ hi,
                             __half* __restrict__ lo, int n8) {
    int i = blockIdx.x * blockDim.x + threadIdx.x;
    if (i >= n8) return;
    const float4* s = (const float4*)src + 2 * (size_t)i;
    float4 v0 = s[0], v1 = s[1];
    uint32_t h0,h1,h2,h3,l0,l1,l2,l3;
    split2h(v0.x, v0.y, h0, l0); split2h(v0.z, v0.w, h1, l1);
    split2h(v1.x, v1.y, h2, l2); split2h(v1.z, v1.w, h3, l3);
    *(uint4*)(hi + 8 * (size_t)i) = make_uint4(h0, h1, h2, h3);
    *(uint4*)(lo + 8 * (size_t)i) = make_uint4(l0, l1, l2, l3);
}
// B-side: fp32 -> fp16 hi only
__global__ void cvt_kernel(const float* __restrict__ src,
                           __half* __restrict__ hi, int n8) {
    int i = blockIdx.x * blockDim.x + threadIdx.x;
    if (i >= n8) return;
    const float4* s = (const float4*)src + 2 * (size_t)i;
    float4 v0 = s[0], v1 = s[1];
    *(uint4*)(hi + 8 * (size_t)i) = make_uint4(
        cvt2h(v0.x, v0.y), cvt2h(v0.z, v0.w), cvt2h(v1.x, v1.y), cvt2h(v1.z, v1.w));
}

// ---------------- routing (proven) ----------------
__global__ void zero_cnt_kernel() { if (threadIdx.x < EXPERTS) g_cnt[threadIdx.x] = 0; }

__global__ void router_logits_kernel(const float* __restrict__ X, const float* __restrict__ Wg) {
    int idx = blockIdx.x * blockDim.x + threadIdx.x;
    int t = idx >> 4, e = idx & 15;
    const float* xr = X + (size_t)t * HIDDEN;
    float s0 = 0.f, s1 = 0.f, s2 = 0.f, s3 = 0.f;
    #pragma unroll 4
    for (int k = 0; k < HIDDEN; k += 4) {
        s0 = fmaf(xr[k+0], Wg[(k+0)*EXPERTS + e], s0);
        s1 = fmaf(xr[k+1], Wg[(k+1)*EXPERTS + e], s1);
        s2 = fmaf(xr[k+2], Wg[(k+2)*EXPERTS + e], s2);
        s3 = fmaf(xr[k+3], Wg[(k+3)*EXPERTS + e], s3);
    }
    g_logits[idx] = (s0 + s1) + (s2 + s3);
}

__global__ void router_topk_kernel() {
    int t = blockIdx.x * blockDim.x + threadIdx.x;
    if (t >= TOKENS) return;
    float l[EXPERTS];
    #pragma unroll
    for (int e = 0; e < EXPERTS; e++) l[e] = g_logits[t * EXPERTS + e];
    int e1 = 0; float v1 = l[0];
    #pragma unroll
    for (int e = 1; e < EXPERTS; e++) if (l[e] > v1) { v1 = l[e]; e1 = e; }
    int e2 = -1; float v2 = -3.4e38f;
    #pragma unroll
    for (int e = 0; e < EXPERTS; e++) { if (e == e1) continue; if (l[e] > v2) { v2 = l[e]; e2 = e; } }
    float w1 = sigmoidf_fast(v1), w2 = sigmoidf_fast(v2);
    float inv = 1.0f / (w1 + w2); w1 *= inv; w2 *= inv;
    int s1 = atomicAdd(&g_cnt[e1], 1);
    int s2 = atomicAdd(&g_cnt[e2], 1);
    g_tok[e1 * TOKENS + s1] = t;
    g_tok[e2 * TOKENS + s2] = t;
    g_te[2*t+0] = e1; g_tslot[2*t+0] = s1; g_tw[2*t+0] = w1;
    g_te[2*t+1] = e2; g_tslot[2*t+1] = s2; g_tw[2*t+1] = w2;
}

__global__ void offsets_kernel() {
    if (threadIdx.x == 0 && blockIdx.x == 0) {
        int a = 0;
        for (int e = 0; e < EXPERTS; e++) { g_off[e] = a; a += g_cnt[e]; }
        g_off[EXPERTS] = a;
    }
}

// ---------------- fp16 2-term mma.sync grouped GEMM, cp.async 3-stage ----------------
// FUSED=1: A = gathered Xh/Xl rows; B0=W0h(gate), B1=W1h(up); epi h=silu(g)*u -> g_hh/g_hl
// FUSED=0: A = g_hh/g_hl rows;      B0=Wdh;                  epi raw -> g_y
template <int FUSED>
__global__ __launch_bounds__(256, 1)
void moe_gemm_fp16(const __half* __restrict__ Agh,
                   const __half* __restrict__ Agl,
                   const __half* __restrict__ B0h_g,
                   const __half* __restrict__ B1h_g) {
    constexpr int Kdim = FUSED ? HIDDEN : INTER;
    constexpr int Ndim = FUSED ? INTER : HIDDEN;
    constexpr int KT   = Kdim / 32;
    constexpr int SA   = 40;   // halves
    constexpr int SB   = 136;  // halves
    constexpr int AH  = 0;
    constexpr int AL  = 128 * SA;          // 5120
    constexpr int B0H = 2 * 128 * SA;      // 10240
    constexpr int B1H = B0H + 32 * SB;
    constexpr int STAGE_H = B0H + (FUSED ? 2 : 1) * 32 * SB;
    constexpr int STAGE_B = STAGE_H * 2;

    const int e  = blockIdx.z;
    const int ne = g_cnt[e];
    const int m0 = blockIdx.x * 128;
    if (m0 >= ne) return;
    const int n0  = blockIdx.y * 128;
    const int off = g_off[e];

    extern __shared__ __align__(16) uint16_t smh[];
    const uint32_t sbase = smem_u32(smh);

    const int tid  = threadIdx.x;
    const int lane = tid & 31;
    const int wid  = tid >> 5;
    const int wm   = wid & 1;
    const int wn   = wid >> 1;
    const int lg   = lane >> 2;
    const int lt   = lane & 3;
    const int q    = lane >> 3;
    const int rr   = lane & 7;

    const uint32_t a_loff = (uint32_t)(((wm * 64 + (q & 1) * 8 + rr) * SA + (q >> 1) * 8) * 2);
    const uint32_t b_loff = (uint32_t)((rr * SB + wn * 32 + q * 8) * 2);

    // A: thread covers row (tid>>1), halves [(tid&1)*16, +16)
    const int ar  = tid >> 1;
    const int ach = (tid & 1) * 16;
    const __half *pAh, *pAl;
    uint32_t aSz;
    {
        int r = m0 + ar;
        if (FUSED) {
            if (r < ne) {
                size_t rb = (size_t)g_tok[e * TOKENS + r] * Kdim + ach;
                pAh = Agh + rb; pAl = Agl + rb; aSz = 16;
            } else { pAh = Agh; pAl = Agl; aSz = 0; }
        } else {
            size_t rb = (size_t)(off + r) * Kdim + ach;
            pAh = Agh + rb; pAl = Agl + rb; aSz = 16;
        }
    }
    const uint32_t dA = (uint32_t)((ar * SA + ach) * 2);
    // B: thread covers k-row (tid>>3), halves [(tid&7)*16, +16)
    const int br  = tid >> 3;
    const int bch = (tid & 7) * 16;
    const size_t bstart = (size_t)e * Kdim * Ndim + (size_t)br * Ndim + n0 + bch;
    const __half* pB0h = B0h_g + bstart;
    const __half* pB1h = FUSED ? (B1h_g + bstart) : nullptr;
    const uint32_t dB = (uint32_t)((br * SB + bch) * 2);

    auto issue = [&](int kt, int buf) {
        const uint32_t st = sbase + (uint32_t)buf * STAGE_B;
        const size_t ak = (size_t)kt * 32;
        const size_t bk = (size_t)kt * 32 * Ndim;
        CP16(st + dA,                 pAh + ak,      aSz);
        CP16(st + dA + 16,            pAh + ak + 8,  aSz);
        CP16(st + dA + AL * 2,        pAl + ak,      aSz);
        CP16(st + dA + AL * 2 + 16,   pAl + ak + 8,  aSz);
        CP16(st + dB + B0H * 2,       pB0h + bk,     16u);
        CP16(st + dB + B0H * 2 + 16,  pB0h + bk + 8, 16u);
        if (FUSED) {
            CP16(st + dB + B1H * 2,       pB1h + bk,     16u);
            CP16(st + dB + B1H * 2 + 16,  pB1h + bk + 8, 16u);
        }
    };

    float accG[4][4][4];
    float accU[FUSED ? 4 : 1][4][4];
    #pragma unroll
    for (int i = 0; i < 4; i++)
        #pragma unroll
        for (int j = 0; j < 4; j++)
            #pragma unroll
            for (int p = 0; p < 4; p++) { accG[i][j][p] = 0.f; if (FUSED) accU[i][j][p] = 0.f; }

    issue(0, 0); CP_COMMIT();
    if (KT > 1) issue(1, 1);
    CP_COMMIT();
    CP_WAIT1();
    __syncthreads();

    for (int kt = 0; kt < KT; kt++) {
        if (kt + 2 < KT) issue(kt + 2, (kt + 2) % 3);
        CP_COMMIT();

        const uint32_t st = sbase + (uint32_t)(kt % 3) * STAGE_B;
        #pragma unroll
        for (int ks = 0; ks < 2; ks++) {
            const uint32_t bks = (uint32_t)(ks * 16 * SB * 2);
            uint32_t bGh[4][2];
            uint32_t bUh[FUSED ? 4 : 1][2];
            {
                uint32_t t0, t1, t2, t3;
                uint32_t ba = st + (uint32_t)(B0H * 2) + b_loff + bks;
                LDSM4T(t0, t1, t2, t3, ba);
                bGh[0][0]=t0; bGh[1][0]=t1; bGh[2][0]=t2; bGh[3][0]=t3;
                LDSM4T(t0, t1, t2, t3, ba + 8 * SB * 2);
                bGh[0][1]=t0; bGh[1][1]=t1; bGh[2][1]=t2; bGh[3][1]=t3;
                if (FUSED) {
                    ba = st + (uint32_t)(B1H * 2) + b_loff + bks;
                    LDSM4T(t0, t1, t2, t3, ba);
                    bUh[0][0]=t0; bUh[1][0]=t1; bUh[2][0]=t2; bUh[3][0]=t3;
                    LDSM4T(t0, t1, t2, t3, ba + 8 * SB * 2);
                    bUh[0][1]=t0; bUh[1][1]=t1; bUh[2][1]=t2; bUh[3][1]=t3;
                }
            }
            #pragma unroll
            for (int mf = 0; mf < 4; mf++) {
                uint32_t ah[4], al[4];
                const uint32_t aa = st + a_loff + (uint32_t)(mf * 16 * SA * 2) + (uint32_t)(ks * 32);
                LDSM4(ah[0], ah[1], ah[2], ah[3], aa + (uint32_t)(AH * 2));
                LDSM4(al[0], al[1], al[2], al[3], aa + (uint32_t)(AL * 2));
                #pragma unroll
                for (int nf = 0; nf < 4; nf++) {
                    mma16(accG[mf][nf], ah, bGh[nf]);
                    mma16(accG[mf][nf], al, bGh[nf]);
                    if (FUSED) {
                        mma16(accU[mf][nf], ah, bUh[nf]);
                        mma16(accU[mf][nf], al, bUh[nf]);
                    }
                }
            }
        }
        CP_WAIT1();
        __syncthreads();
    }

    // ---- epilogue ----
    #pragma unroll
    for (int mf = 0; mf < 4; mf++) {
        #pragma unroll
        for (int h = 0; h < 2; h++) {
            int r = m0 + wm * 64 + mf * 16 + lg + h * 8;
            if (r >= ne) continue;
            int col = n0 + wn * 32 + lt * 2;
            if (FUSED) {
                size_t base = (size_t)(off + r) * INTER + col;
                #pragma unroll
                for (int nf = 0; nf < 4; nf++) {
                    float g0 = accG[mf][nf][2*h],   g1 = accG[mf][nf][2*h+1];
                    float u0 = accU[mf][nf][2*h],   u1 = accU[mf][nf][2*h+1];
                    float h0 = g0 * sigmoidf_fast(g0) * u0;
                    float h1 = g1 * sigmoidf_fast(g1) * u1;
                    uint32_t hh, hl;
                    split2h(h0, h1, hh, hl);
                    *(uint32_t*)(g_hh + base + nf * 8) = hh;
                    *(uint32_t*)(g_hl + base + nf * 8) = hl;
                }
            } else {
                float* orow = g_y + (size_t)(off + r) * HIDDEN + col;
                #pragma unroll
                for (int nf = 0; nf < 4; nf++) {
                    float2 v = make_float2(accG[mf][nf][2*h], accG[mf][nf][2*h+1]);
                    *(float2*)(orow + nf * 8) = v;
                }
            }
        }
    }
}

// ---------------- combine ----------------
__global__ void combine_kernel(float* __restrict__ out) {
    int idx = blockIdx.x * blockDim.x + threadIdx.x;
    int t = idx / (HIDDEN / 4);
    int c = idx % (HIDDEN / 4);
    int e0 = g_te[2*t], e1 = g_te[2*t+1];
    size_t p0 = (size_t)g_off[e0] + g_tslot[2*t];
    size_t p1 = (size_t)g_off[e1] + g_tslot[2*t+1];
    float w0 = g_tw[2*t], w1 = g_tw[2*t+1];
    float4 y0 = *(const float4*)(g_y + p0 * HIDDEN + 4*c);
    float4 y1 = *(const float4*)(g_y + p1 * HIDDEN + 4*c);
    float4 r;
    r.x = w0*y0.x + w1*y1.x; r.y = w0*y0.y + w1*y1.y;
    r.z = w0*y0.z + w1*y1.z; r.w = w0*y0.w + w1*y1.w;
    *(float4*)(out + (size_t)t * HIDDEN + 4*c) = r;
}

// ---------------- launcher ----------------
extern "C" void kernel_launch(void* const* d_in, const int* in_sizes, int n_in,
                              void* d_out, int out_size) {
    const float* X   = (const float*)d_in[0];
    const float* Wg  = (const float*)d_in[1];
    const float* Wgp = (const float*)d_in[2];
    const float* Wup = (const float*)d_in[3];
    const float* Wdp = (const float*)d_in[4];
    float* out = (float*)d_out;

    __half *xh, *xl, *w0h, *w1h, *wdh, *hh, *hl;
    cudaGetSymbolAddress((void**)&xh,  c_Xh);  cudaGetSymbolAddress((void**)&xl,  c_Xl);
    cudaGetSymbolAddress((void**)&w0h, c_W0h);
    cudaGetSymbolAddress((void**)&w1h, c_W1h);
    cudaGetSymbolAddress((void**)&wdh, c_Wdh);
    cudaGetSymbolAddress((void**)&hh,  g_hh);  cudaGetSymbolAddress((void**)&hl,  g_hl);

    constexpr int STAGE_F = (2*128*40 + 2*32*136) * 2;   // 37888 B
    constexpr int STAGE_D = (2*128*40 + 1*32*136) * 2;   // 29184 B
    const int SMEM_F = 3 * STAGE_F;                      // 113664
    const int SMEM_D = 3 * STAGE_D;                      // 87552
    cudaFuncSetAttribute(moe_gemm_fp16<1>, cudaFuncAttributeMaxDynamicSharedMemorySize, SMEM_F);
    cudaFuncSetAttribute(moe_gemm_fp16<0>, cudaFuncAttributeMaxDynamicSharedMemorySize, SMEM_D);

    // routing
    zero_cnt_kernel<<<1, 32>>>();
    router_logits_kernel<<<(TOKENS * EXPERTS) / 256, 256>>>(X, Wg);
    router_topk_kernel<<<(TOKENS + 255) / 256, 256>>>();
    offsets_kernel<<<1, 1>>>();

    // operand conversion
    const int NX = TOKENS * HIDDEN / 8;
    const int NW = EXPERTS * HIDDEN * INTER / 8;
    split_kernel<<<(NX + 255) / 256, 256>>>(X,   xh,  xl,  NX);
    cvt_kernel<<<(NW + 255) / 256, 256>>>(Wgp, w0h, NW);
    cvt_kernel<<<(NW + 255) / 256, 256>>>(Wup, w1h, NW);
    cvt_kernel<<<(NW + 255) / 256, 256>>>(Wdp, wdh, NW);

    // fused gate+up GEMM + SwiGLU
    dim3 grid_f(TOKENS / 128, INTER / 128, EXPERTS);
    moe_gemm_fp16<1><<<grid_f, 256, SMEM_F>>>(xh, xl, w0h, w1h);

    // down GEMM
    dim3 grid_d(TOKENS / 128, HIDDEN / 128, EXPERTS);
    moe_gemm_fp16<0><<<grid_d, 256, SMEM_D>>>(hh, hl, wdh, nullptr);

    combine_kernel<<<(TOKENS * (HIDDEN / 4)) / 256, 256>>>(out);
}

// round 8
// speedup vs baseline: 3.6356x; 1.4191x over previous
#include <cuda_runtime.h>
#include <cuda_fp16.h>
#include <cstdint>
#include <math.h>

#define TOKENS  2048
#define HIDDEN  2048
#define INTER   1408
#define EXPERTS 16
#define MAXPAIRS (TOKENS*2)

// ---------------- scratch ----------------
__device__ int   g_cnt[EXPERTS];
__device__ int   g_off[EXPERTS + 1];
__device__ int   g_tok[EXPERTS * TOKENS];
__device__ int   g_te[MAXPAIRS];
__device__ int   g_tslot[MAXPAIRS];
__device__ float g_tw[MAXPAIRS];
__device__ float g_logits[TOKENS * EXPERTS];
__device__ float g_y[(size_t)MAXPAIRS * HIDDEN];

// fp16 operands (single-term)
__device__ __half c_Xh[(size_t)TOKENS * HIDDEN];
__device__ __half c_W0h[(size_t)EXPERTS * HIDDEN * INTER];
__device__ __half c_W1h[(size_t)EXPERTS * HIDDEN * INTER];
__device__ __half c_Wdh[(size_t)EXPERTS * INTER * HIDDEN];
__device__ __half g_hh[(size_t)(MAXPAIRS + 128) * INTER];

// ---------------- helpers ----------------
__device__ __forceinline__ float sigmoidf_fast(float x) { return 1.0f / (1.0f + __expf(-x)); }

__device__ __forceinline__ uint32_t smem_u32(const void* p) {
    uint32_t a;
    asm("{ .reg .u64 t; cvta.to.shared.u64 t, %1; cvt.u32.u64 %0, t; }" : "=r"(a) : "l"(p));
    return a;
}
__device__ __forceinline__ uint32_t cvt2h(float x, float y) {
    __half2 h = __floats2half2_rn(x, y);
    return *(uint32_t*)&h;
}
// m16n8k16 fp16 MMA, fp32 accum
__device__ __forceinline__ void mma16(float* d, const uint32_t* a, const uint32_t* b) {
    asm volatile("mma.sync.aligned.m16n8k16.row.col.f32.f16.f16.f32 "
        "{%0,%1,%2,%3}, {%4,%5,%6,%7}, {%8,%9}, {%0,%1,%2,%3};"
        : "+f"(d[0]), "+f"(d[1]), "+f"(d[2]), "+f"(d[3])
        : "r"(a[0]), "r"(a[1]), "r"(a[2]), "r"(a[3]), "r"(b[0]), "r"(b[1]));
}
#define LDSM4(r0,r1,r2,r3,addr) \
    asm volatile("ldmatrix.sync.aligned.m8n8.x4.shared.b16 {%0,%1,%2,%3}, [%4];" \
        : "=r"(r0), "=r"(r1), "=r"(r2), "=r"(r3) : "r"(addr))
#define LDSM4T(r0,r1,r2,r3,addr) \
    asm volatile("ldmatrix.sync.aligned.m8n8.x4.trans.shared.b16 {%0,%1,%2,%3}, [%4];" \
        : "=r"(r0), "=r"(r1), "=r"(r2), "=r"(r3) : "r"(addr))
#define CP16(dst, src, sz) \
    asm volatile("cp.async.cg.shared.global [%0], [%1], 16, %2;" \
        :: "r"(dst), "l"(src), "r"(sz) : "memory")
#define CP_COMMIT() asm volatile("cp.async.commit_group;" ::: "memory")
#define CP_WAIT1()  asm volatile("cp.async.wait_group 1;" ::: "memory")

// ---------------- conversion: fp32 -> fp16 ----------------
__global__ void cvt_kernel(const float* __restrict__ src,
                           __half* __restrict__ dst, int n8) {
    int i = blockIdx.x * blockDim.x + threadIdx.x;
    if (i >= n8) return;
    const float4* s = (const float4*)src + 2 * (size_t)i;
    float4 v0 = s[0], v1 = s[1];
    *(uint4*)(dst + 8 * (size_t)i) = make_uint4(
        cvt2h(v0.x, v0.y), cvt2h(v0.z, v0.w), cvt2h(v1.x, v1.y), cvt2h(v1.z, v1.w));
}

// ---------------- routing (proven) ----------------
__global__ void zero_cnt_kernel() { if (threadIdx.x < EXPERTS) g_cnt[threadIdx.x] = 0; }

__global__ void router_logits_kernel(const float* __restrict__ X, const float* __restrict__ Wg) {
    int idx = blockIdx.x * blockDim.x + threadIdx.x;
    int t = idx >> 4, e = idx & 15;
    const float* xr = X + (size_t)t * HIDDEN;
    float s0 = 0.f, s1 = 0.f, s2 = 0.f, s3 = 0.f;
    #pragma unroll 4
    for (int k = 0; k < HIDDEN; k += 4) {
        s0 = fmaf(xr[k+0], Wg[(k+0)*EXPERTS + e], s0);
        s1 = fmaf(xr[k+1], Wg[(k+1)*EXPERTS + e], s1);
        s2 = fmaf(xr[k+2], Wg[(k+2)*EXPERTS + e], s2);
        s3 = fmaf(xr[k+3], Wg[(k+3)*EXPERTS + e], s3);
    }
    g_logits[idx] = (s0 + s1) + (s2 + s3);
}

__global__ void router_topk_kernel() {
    int t = blockIdx.x * blockDim.x + threadIdx.x;
    if (t >= TOKENS) return;
    float l[EXPERTS];
    #pragma unroll
    for (int e = 0; e < EXPERTS; e++) l[e] = g_logits[t * EXPERTS + e];
    int e1 = 0; float v1 = l[0];
    #pragma unroll
    for (int e = 1; e < EXPERTS; e++) if (l[e] > v1) { v1 = l[e]; e1 = e; }
    int e2 = -1; float v2 = -3.4e38f;
    #pragma unroll
    for (int e = 0; e < EXPERTS; e++) { if (e == e1) continue; if (l[e] > v2) { v2 = l[e]; e2 = e; } }
    float w1 = sigmoidf_fast(v1), w2 = sigmoidf_fast(v2);
    float inv = 1.0f / (w1 + w2); w1 *= inv; w2 *= inv;
    int s1 = atomicAdd(&g_cnt[e1], 1);
    int s2 = atomicAdd(&g_cnt[e2], 1);
    g_tok[e1 * TOKENS + s1] = t;
    g_tok[e2 * TOKENS + s2] = t;
    g_te[2*t+0] = e1; g_tslot[2*t+0] = s1; g_tw[2*t+0] = w1;
    g_te[2*t+1] = e2; g_tslot[2*t+1] = s2; g_tw[2*t+1] = w2;
}

__global__ void offsets_kernel() {
    if (threadIdx.x == 0 && blockIdx.x == 0) {
        int a = 0;
        for (int e = 0; e < EXPERTS; e++) { g_off[e] = a; a += g_cnt[e]; }
        g_off[EXPERTS] = a;
    }
}

// ---------------- fp16 single-term mma.sync grouped GEMM, cp.async 3-stage ----------------
// FUSED=1: A = gathered Xh rows; B0=W0h(gate), B1=W1h(up); epi h=silu(g)*u -> g_hh (fp16)
// FUSED=0: A = g_hh rows;        B0=Wdh;                   epi raw -> g_y (fp32)
template <int FUSED>
__global__ __launch_bounds__(256, 1)
void moe_gemm_fp16(const __half* __restrict__ Agh,
                   const __half* __restrict__ B0h_g,
                   const __half* __restrict__ B1h_g) {
    constexpr int Kdim = FUSED ? HIDDEN : INTER;
    constexpr int Ndim = FUSED ? INTER : HIDDEN;
    constexpr int KT   = Kdim / 32;
    constexpr int SA   = 40;   // halves
    constexpr int SB   = 136;  // halves
    constexpr int B0H  = 128 * SA;          // 5120
    constexpr int B1H  = B0H + 32 * SB;
    constexpr int STAGE_H = B0H + (FUSED ? 2 : 1) * 32 * SB;
    constexpr int STAGE_B = STAGE_H * 2;

    const int e  = blockIdx.z;
    const int ne = g_cnt[e];
    const int m0 = blockIdx.x * 128;
    if (m0 >= ne) return;
    const int n0  = blockIdx.y * 128;
    const int off = g_off[e];

    extern __shared__ __align__(16) uint16_t smh[];
    const uint32_t sbase = smem_u32(smh);

    const int tid  = threadIdx.x;
    const int lane = tid & 31;
    const int wid  = tid >> 5;
    const int wm   = wid & 1;
    const int wn   = wid >> 1;
    const int lg   = lane >> 2;
    const int lt   = lane & 3;
    const int q    = lane >> 3;
    const int rr   = lane & 7;

    const uint32_t a_loff = (uint32_t)(((wm * 64 + (q & 1) * 8 + rr) * SA + (q >> 1) * 8) * 2);
    const uint32_t b_loff = (uint32_t)((rr * SB + wn * 32 + q * 8) * 2);

    // A: thread covers row (tid>>1), halves [(tid&1)*16, +16)
    const int ar  = tid >> 1;
    const int ach = (tid & 1) * 16;
    const __half* pAh;
    uint32_t aSz;
    {
        int r = m0 + ar;
        if (FUSED) {
            if (r < ne) {
                pAh = Agh + (size_t)g_tok[e * TOKENS + r] * Kdim + ach; aSz = 16;
            } else { pAh = Agh; aSz = 0; }
        } else {
            pAh = Agh + (size_t)(off + r) * Kdim + ach; aSz = 16;
        }
    }
    const uint32_t dA = (uint32_t)((ar * SA + ach) * 2);
    // B: thread covers k-row (tid>>3), halves [(tid&7)*16, +16)
    const int br  = tid >> 3;
    const int bch = (tid & 7) * 16;
    const size_t bstart = (size_t)e * Kdim * Ndim + (size_t)br * Ndim + n0 + bch;
    const __half* pB0h = B0h_g + bstart;
    const __half* pB1h = FUSED ? (B1h_g + bstart) : nullptr;
    const uint32_t dB = (uint32_t)((br * SB + bch) * 2);

    auto issue = [&](int kt, int buf) {
        const uint32_t st = sbase + (uint32_t)buf * STAGE_B;
        const size_t ak = (size_t)kt * 32;
        const size_t bk = (size_t)kt * 32 * Ndim;
        CP16(st + dA,                 pAh + ak,      aSz);
        CP16(st + dA + 16,            pAh + ak + 8,  aSz);
        CP16(st + dB + B0H * 2,       pB0h + bk,     16u);
        CP16(st + dB + B0H * 2 + 16,  pB0h + bk + 8, 16u);
        if (FUSED) {
            CP16(st + dB + B1H * 2,       pB1h + bk,     16u);
            CP16(st + dB + B1H * 2 + 16,  pB1h + bk + 8, 16u);
        }
    };

    float accG[4][4][4];
    float accU[FUSED ? 4 : 1][4][4];
    #pragma unroll
    for (int i = 0; i < 4; i++)
        #pragma unroll
        for (int j = 0; j < 4; j++)
            #pragma unroll
            for (int p = 0; p < 4; p++) { accG[i][j][p] = 0.f; if (FUSED) accU[i][j][p] = 0.f; }

    issue(0, 0); CP_COMMIT();
    if (KT > 1) issue(1, 1);
    CP_COMMIT();
    CP_WAIT1();
    __syncthreads();

    for (int kt = 0; kt < KT; kt++) {
        if (kt + 2 < KT) issue(kt + 2, (kt + 2) % 3);
        CP_COMMIT();

        const uint32_t st = sbase + (uint32_t)(kt % 3) * STAGE_B;
        #pragma unroll
        for (int ks = 0; ks < 2; ks++) {
            const uint32_t bks = (uint32_t)(ks * 16 * SB * 2);
            uint32_t bGh[4][2];
            uint32_t bUh[FUSED ? 4 : 1][2];
            {
                uint32_t t0, t1, t2, t3;
                uint32_t ba = st + (uint32_t)(B0H * 2) + b_loff + bks;
                LDSM4T(t0, t1, t2, t3, ba);
                bGh[0][0]=t0; bGh[1][0]=t1; bGh[2][0]=t2; bGh[3][0]=t3;
                LDSM4T(t0, t1, t2, t3, ba + 8 * SB * 2);
                bGh[0][1]=t0; bGh[1][1]=t1; bGh[2][1]=t2; bGh[3][1]=t3;
                if (FUSED) {
                    ba = st + (uint32_t)(B1H * 2) + b_loff + bks;
                    LDSM4T(t0, t1, t2, t3, ba);
                    bUh[0][0]=t0; bUh[1][0]=t1; bUh[2][0]=t2; bUh[3][0]=t3;
                    LDSM4T(t0, t1, t2, t3, ba + 8 * SB * 2);
                    bUh[0][1]=t0; bUh[1][1]=t1; bUh[2][1]=t2; bUh[3][1]=t3;
                }
            }
            #pragma unroll
            for (int mf = 0; mf < 4; mf++) {
                uint32_t ah[4];
                const uint32_t aa = st + a_loff + (uint32_t)(mf * 16 * SA * 2) + (uint32_t)(ks * 32);
                LDSM4(ah[0], ah[1], ah[2], ah[3], aa);
                #pragma unroll
                for (int nf = 0; nf < 4; nf++) {
                    mma16(accG[mf][nf], ah, bGh[nf]);
                    if (FUSED) mma16(accU[mf][nf], ah, bUh[nf]);
                }
            }
        }
        CP_WAIT1();
        __syncthreads();
    }

    // ---- epilogue ----
    #pragma unroll
    for (int mf = 0; mf < 4; mf++) {
        #pragma unroll
        for (int h = 0; h < 2; h++) {
            int r = m0 + wm * 64 + mf * 16 + lg + h * 8;
            if (r >= ne) continue;
            int col = n0 + wn * 32 + lt * 2;
            if (FUSED) {
                size_t base = (size_t)(off + r) * INTER + col;
                #pragma unroll
                for (int nf = 0; nf < 4; nf++) {
                    float g0 = accG[mf][nf][2*h],   g1 = accG[mf][nf][2*h+1];
                    float u0 = accU[mf][nf][2*h],   u1 = accU[mf][nf][2*h+1];
                    float h0 = g0 * sigmoidf_fast(g0) * u0;
                    float h1 = g1 * sigmoidf_fast(g1) * u1;
                    *(uint32_t*)(g_hh + base + nf * 8) = cvt2h(h0, h1);
                }
            } else {
                float* orow = g_y + (size_t)(off + r) * HIDDEN + col;
                #pragma unroll
                for (int nf = 0; nf < 4; nf++) {
                    float2 v = make_float2(accG[mf][nf][2*h], accG[mf][nf][2*h+1]);
                    *(float2*)(orow + nf * 8) = v;
                }
            }
        }
    }
}

// ---------------- combine ----------------
__global__ void combine_kernel(float* __restrict__ out) {
    int idx = blockIdx.x * blockDim.x + threadIdx.x;
    int t = idx / (HIDDEN / 4);
    int c = idx % (HIDDEN / 4);
    int e0 = g_te[2*t], e1 = g_te[2*t+1];
    size_t p0 = (size_t)g_off[e0] + g_tslot[2*t];
    size_t p1 = (size_t)g_off[e1] + g_tslot[2*t+1];
    float w0 = g_tw[2*t], w1 = g_tw[2*t+1];
    float4 y0 = *(const float4*)(g_y + p0 * HIDDEN + 4*c);
    float4 y1 = *(const float4*)(g_y + p1 * HIDDEN + 4*c);
    float4 r;
    r.x = w0*y0.x + w1*y1.x; r.y = w0*y0.y + w1*y1.y;
    r.z = w0*y0.z + w1*y1.z; r.w = w0*y0.w + w1*y1.w;
    *(float4*)(out + (size_t)t * HIDDEN + 4*c) = r;
}

// ---------------- launcher ----------------
extern "C" void kernel_launch(void* const* d_in, const int* in_sizes, int n_in,
                              void* d_out, int out_size) {
    const float* X   = (const float*)d_in[0];
    const float* Wg  = (const float*)d_in[1];
    const float* Wgp = (const float*)d_in[2];
    const float* Wup = (const float*)d_in[3];
    const float* Wdp = (const float*)d_in[4];
    float* out = (float*)d_out;

    __half *xh, *w0h, *w1h, *wdh, *hh;
    cudaGetSymbolAddress((void**)&xh,  c_Xh);
    cudaGetSymbolAddress((void**)&w0h, c_W0h);
    cudaGetSymbolAddress((void**)&w1h, c_W1h);
    cudaGetSymbolAddress((void**)&wdh, c_Wdh);
    cudaGetSymbolAddress((void**)&hh,  g_hh);

    constexpr int STAGE_F = (128*40 + 2*32*136) * 2;   // 27648 B
    constexpr int STAGE_D = (128*40 + 1*32*136) * 2;   // 18944 B
    const int SMEM_F = 3 * STAGE_F;                    // 82944
    const int SMEM_D = 3 * STAGE_D;                    // 56832
    cudaFuncSetAttribute(moe_gemm_fp16<1>, cudaFuncAttributeMaxDynamicSharedMemorySize, SMEM_F);
    cudaFuncSetAttribute(moe_gemm_fp16<0>, cudaFuncAttributeMaxDynamicSharedMemorySize, SMEM_D);

    // routing
    zero_cnt_kernel<<<1, 32>>>();
    router_logits_kernel<<<(TOKENS * EXPERTS) / 256, 256>>>(X, Wg);
    router_topk_kernel<<<(TOKENS + 255) / 256, 256>>>();
    offsets_kernel<<<1, 1>>>();

    // operand conversion fp32 -> fp16
    const int NX = TOKENS * HIDDEN / 8;
    const int NW = EXPERTS * HIDDEN * INTER / 8;
    cvt_kernel<<<(NX + 255) / 256, 256>>>(X,   xh,  NX);
    cvt_kernel<<<(NW + 255) / 256, 256>>>(Wgp, w0h, NW);
    cvt_kernel<<<(NW + 255) / 256, 256>>>(Wup, w1h, NW);
    cvt_kernel<<<(NW + 255) / 256, 256>>>(Wdp, wdh, NW);

    // fused gate+up GEMM + SwiGLU
    dim3 grid_f(TOKENS / 128, INTER / 128, EXPERTS);
    moe_gemm_fp16<1><<<grid_f, 256, SMEM_F>>>(xh, w0h, w1h);

    // down GEMM
    dim3 grid_d(TOKENS / 128, HIDDEN / 128, EXPERTS);
    moe_gemm_fp16<0><<<grid_d, 256, SMEM_D>>>(hh, wdh, nullptr);

    combine_kernel<<<(TOKENS * (HIDDEN / 4)) / 256, 256>>>(out);
}

// round 9
// speedup vs baseline: 3.8349x; 1.0548x over previous
#include <cuda_runtime.h>
#include <cuda_fp16.h>
#include <cstdint>
#include <math.h>

#define TOKENS  2048
#define HIDDEN  2048
#define INTER   1408
#define EXPERTS 16
#define MAXPAIRS (TOKENS*2)

// ---------------- scratch ----------------
__device__ int   g_cnt[EXPERTS];
__device__ int   g_off[EXPERTS + 1];
__device__ int   g_tok[EXPERTS * TOKENS];
__device__ int   g_te[MAXPAIRS];
__device__ int   g_tslot[MAXPAIRS];
__device__ float g_tw[MAXPAIRS];
__device__ float g_logits[TOKENS * EXPERTS];
__device__ float g_y[(size_t)MAXPAIRS * HIDDEN];

// fp16 operands (single-term)
__device__ __half c_Xh[(size_t)TOKENS * HIDDEN];
__device__ __half c_W0h[(size_t)EXPERTS * HIDDEN * INTER];
__device__ __half c_W1h[(size_t)EXPERTS * HIDDEN * INTER];
__device__ __half c_Wdh[(size_t)EXPERTS * INTER * HIDDEN];
__device__ __half g_hh[(size_t)(MAXPAIRS + 128) * INTER];

// ---------------- helpers ----------------
__device__ __forceinline__ float sigmoidf_fast(float x) { return 1.0f / (1.0f + __expf(-x)); }

__device__ __forceinline__ uint32_t smem_u32(const void* p) {
    uint32_t a;
    asm("{ .reg .u64 t; cvta.to.shared.u64 t, %1; cvt.u32.u64 %0, t; }" : "=r"(a) : "l"(p));
    return a;
}
__device__ __forceinline__ uint32_t cvt2h(float x, float y) {
    __half2 h = __floats2half2_rn(x, y);
    return *(uint32_t*)&h;
}
// m16n8k16 fp16 MMA, fp32 accum
__device__ __forceinline__ void mma16(float* d, const uint32_t* a, const uint32_t* b) {
    asm volatile("mma.sync.aligned.m16n8k16.row.col.f32.f16.f16.f32 "
        "{%0,%1,%2,%3}, {%4,%5,%6,%7}, {%8,%9}, {%0,%1,%2,%3};"
        : "+f"(d[0]), "+f"(d[1]), "+f"(d[2]), "+f"(d[3])
        : "r"(a[0]), "r"(a[1]), "r"(a[2]), "r"(a[3]), "r"(b[0]), "r"(b[1]));
}
#define LDSM4(r0,r1,r2,r3,addr) \
    asm volatile("ldmatrix.sync.aligned.m8n8.x4.shared.b16 {%0,%1,%2,%3}, [%4];" \
        : "=r"(r0), "=r"(r1), "=r"(r2), "=r"(r3) : "r"(addr))
#define LDSM4T(r0,r1,r2,r3,addr) \
    asm volatile("ldmatrix.sync.aligned.m8n8.x4.trans.shared.b16 {%0,%1,%2,%3}, [%4];" \
        : "=r"(r0), "=r"(r1), "=r"(r2), "=r"(r3) : "r"(addr))
#define CP16(dst, src, sz) \
    asm volatile("cp.async.cg.shared.global [%0], [%1], 16, %2;" \
        :: "r"(dst), "l"(src), "r"(sz) : "memory")
#define CP_COMMIT() asm volatile("cp.async.commit_group;" ::: "memory")
#define CP_WAIT1()  asm volatile("cp.async.wait_group 1;" ::: "memory")

// ---------------- conversion: fp32 -> fp16 ----------------
__global__ void cvt_kernel(const float* __restrict__ src,
                           __half* __restrict__ dst, int n8) {
    int i = blockIdx.x * blockDim.x + threadIdx.x;
    if (i >= n8) return;
    const float4* s = (const float4*)src + 2 * (size_t)i;
    float4 v0 = s[0], v1 = s[1];
    *(uint4*)(dst + 8 * (size_t)i) = make_uint4(
        cvt2h(v0.x, v0.y), cvt2h(v0.z, v0.w), cvt2h(v1.x, v1.y), cvt2h(v1.z, v1.w));
}

// ---------------- routing (proven) ----------------
__global__ void zero_cnt_kernel() { if (threadIdx.x < EXPERTS) g_cnt[threadIdx.x] = 0; }

__global__ void router_logits_kernel(const float* __restrict__ X, const float* __restrict__ Wg) {
    int idx = blockIdx.x * blockDim.x + threadIdx.x;
    int t = idx >> 4, e = idx & 15;
    const float* xr = X + (size_t)t * HIDDEN;
    float s0 = 0.f, s1 = 0.f, s2 = 0.f, s3 = 0.f;
    #pragma unroll 4
    for (int k = 0; k < HIDDEN; k += 4) {
        s0 = fmaf(xr[k+0], Wg[(k+0)*EXPERTS + e], s0);
        s1 = fmaf(xr[k+1], Wg[(k+1)*EXPERTS + e], s1);
        s2 = fmaf(xr[k+2], Wg[(k+2)*EXPERTS + e], s2);
        s3 = fmaf(xr[k+3], Wg[(k+3)*EXPERTS + e], s3);
    }
    g_logits[idx] = (s0 + s1) + (s2 + s3);
}

__global__ void router_topk_kernel() {
    int t = blockIdx.x * blockDim.x + threadIdx.x;
    if (t >= TOKENS) return;
    float l[EXPERTS];
    #pragma unroll
    for (int e = 0; e < EXPERTS; e++) l[e] = g_logits[t * EXPERTS + e];
    int e1 = 0; float v1 = l[0];
    #pragma unroll
    for (int e = 1; e < EXPERTS; e++) if (l[e] > v1) { v1 = l[e]; e1 = e; }
    int e2 = -1; float v2 = -3.4e38f;
    #pragma unroll
    for (int e = 0; e < EXPERTS; e++) { if (e == e1) continue; if (l[e] > v2) { v2 = l[e]; e2 = e; } }
    float w1 = sigmoidf_fast(v1), w2 = sigmoidf_fast(v2);
    float inv = 1.0f / (w1 + w2); w1 *= inv; w2 *= inv;
    int s1 = atomicAdd(&g_cnt[e1], 1);
    int s2 = atomicAdd(&g_cnt[e2], 1);
    g_tok[e1 * TOKENS + s1] = t;
    g_tok[e2 * TOKENS + s2] = t;
    g_te[2*t+0] = e1; g_tslot[2*t+0] = s1; g_tw[2*t+0] = w1;
    g_te[2*t+1] = e2; g_tslot[2*t+1] = s2; g_tw[2*t+1] = w2;
}

__global__ void offsets_kernel() {
    if (threadIdx.x == 0 && blockIdx.x == 0) {
        int a = 0;
        for (int e = 0; e < EXPERTS; e++) { g_off[e] = a; a += g_cnt[e]; }
        g_off[EXPERTS] = a;
    }
}

// ---------------- fp16 single-term mma.sync grouped GEMM, cp.async 3-stage ----------------
// FUSED=1: A = gathered Xh rows; B0=W0h(gate), B1=W1h(up); epi h=silu(g)*u -> g_hh (fp16)
// FUSED=0: A = g_hh rows;        B0=Wdh;                   epi raw -> g_y (fp32)
template <int FUSED>
__global__ __launch_bounds__(256, 1)
void moe_gemm_fp16(const __half* __restrict__ Agh,
                   const __half* __restrict__ B0h_g,
                   const __half* __restrict__ B1h_g) {
    constexpr int Kdim = FUSED ? HIDDEN : INTER;
    constexpr int Ndim = FUSED ? INTER : HIDDEN;
    constexpr int KT   = Kdim / 32;
    constexpr int SA   = 40;   // halves
    constexpr int SB   = 136;  // halves
    constexpr int B0H  = 128 * SA;          // 5120
    constexpr int B1H  = B0H + 32 * SB;
    constexpr int STAGE_H = B0H + (FUSED ? 2 : 1) * 32 * SB;
    constexpr int STAGE_B = STAGE_H * 2;

    const int e  = blockIdx.z;
    const int ne = g_cnt[e];
    const int m0 = blockIdx.x * 128;
    if (m0 >= ne) return;
    const int n0  = blockIdx.y * 128;
    const int off = g_off[e];

    extern __shared__ __align__(16) uint16_t smh[];
    const uint32_t sbase = smem_u32(smh);

    const int tid  = threadIdx.x;
    const int lane = tid & 31;
    const int wid  = tid >> 5;
    const int wm   = wid & 1;
    const int wn   = wid >> 1;
    const int lg   = lane >> 2;
    const int lt   = lane & 3;
    const int q    = lane >> 3;
    const int rr   = lane & 7;

    const uint32_t a_loff = (uint32_t)(((wm * 64 + (q & 1) * 8 + rr) * SA + (q >> 1) * 8) * 2);
    const uint32_t b_loff = (uint32_t)((rr * SB + wn * 32 + q * 8) * 2);

    // A: thread covers row (tid>>1), halves [(tid&1)*16, +16)
    const int ar  = tid >> 1;
    const int ach = (tid & 1) * 16;
    const __half* pAh;
    uint32_t aSz;
    {
        int r = m0 + ar;
        if (FUSED) {
            if (r < ne) {
                pAh = Agh + (size_t)g_tok[e * TOKENS + r] * Kdim + ach; aSz = 16;
            } else { pAh = Agh; aSz = 0; }
        } else {
            pAh = Agh + (size_t)(off + r) * Kdim + ach; aSz = 16;
        }
    }
    const uint32_t dA = (uint32_t)((ar * SA + ach) * 2);
    // B: thread covers k-row (tid>>3), halves [(tid&7)*16, +16)
    const int br  = tid >> 3;
    const int bch = (tid & 7) * 16;
    const size_t bstart = (size_t)e * Kdim * Ndim + (size_t)br * Ndim + n0 + bch;
    const __half* pB0h = B0h_g + bstart;
    const __half* pB1h = FUSED ? (B1h_g + bstart) : nullptr;
    const uint32_t dB = (uint32_t)((br * SB + bch) * 2);

    auto issue = [&](int kt, int buf) {
        const uint32_t st = sbase + (uint32_t)buf * STAGE_B;
        const size_t ak = (size_t)kt * 32;
        const size_t bk = (size_t)kt * 32 * Ndim;
        CP16(st + dA,                 pAh + ak,      aSz);
        CP16(st + dA + 16,            pAh + ak + 8,  aSz);
        CP16(st + dB + B0H * 2,       pB0h + bk,     16u);
        CP16(st + dB + B0H * 2 + 16,  pB0h + bk + 8, 16u);
        if (FUSED) {
            CP16(st + dB + B1H * 2,       pB1h + bk,     16u);
            CP16(st + dB + B1H * 2 + 16,  pB1h + bk + 8, 16u);
        }
    };

    float accG[4][4][4];
    float accU[FUSED ? 4 : 1][4][4];
    #pragma unroll
    for (int i = 0; i < 4; i++)
        #pragma unroll
        for (int j = 0; j < 4; j++)
            #pragma unroll
            for (int p = 0; p < 4; p++) { accG[i][j][p] = 0.f; if (FUSED) accU[i][j][p] = 0.f; }

    issue(0, 0); CP_COMMIT();
    if (KT > 1) issue(1, 1);
    CP_COMMIT();
    CP_WAIT1();
    __syncthreads();

    for (int kt = 0; kt < KT; kt++) {
        if (kt + 2 < KT) issue(kt + 2, (kt + 2) % 3);
        CP_COMMIT();

        const uint32_t st = sbase + (uint32_t)(kt % 3) * STAGE_B;
        #pragma unroll
        for (int ks = 0; ks < 2; ks++) {
            const uint32_t bks = (uint32_t)(ks * 16 * SB * 2);
            uint32_t bGh[4][2];
            uint32_t bUh[FUSED ? 4 : 1][2];
            {
                uint32_t t0, t1, t2, t3;
                uint32_t ba = st + (uint32_t)(B0H * 2) + b_loff + bks;
                LDSM4T(t0, t1, t2, t3, ba);
                bGh[0][0]=t0; bGh[1][0]=t1; bGh[2][0]=t2; bGh[3][0]=t3;
                LDSM4T(t0, t1, t2, t3, ba + 8 * SB * 2);
                bGh[0][1]=t0; bGh[1][1]=t1; bGh[2][1]=t2; bGh[3][1]=t3;
                if (FUSED) {
                    ba = st + (uint32_t)(B1H * 2) + b_loff + bks;
                    LDSM4T(t0, t1, t2, t3, ba);
                    bUh[0][0]=t0; bUh[1][0]=t1; bUh[2][0]=t2; bUh[3][0]=t3;
                    LDSM4T(t0, t1, t2, t3, ba + 8 * SB * 2);
                    bUh[0][1]=t0; bUh[1][1]=t1; bUh[2][1]=t2; bUh[3][1]=t3;
                }
            }
            #pragma unroll
            for (int mf = 0; mf < 4; mf++) {
                uint32_t ah[4];
                const uint32_t aa = st + a_loff + (uint32_t)(mf * 16 * SA * 2) + (uint32_t)(ks * 32);
                LDSM4(ah[0], ah[1], ah[2], ah[3], aa);
                #pragma unroll
                for (int nf = 0; nf < 4; nf++) {
                    mma16(accG[mf][nf], ah, bGh[nf]);
                    if (FUSED) mma16(accU[mf][nf], ah, bUh[nf]);
                }
            }
        }
        CP_WAIT1();
        __syncthreads();
    }

    // ---- epilogue ----
    #pragma unroll
    for (int mf = 0; mf < 4; mf++) {
        #pragma unroll
        for (int h = 0; h < 2; h++) {
            int r = m0 + wm * 64 + mf * 16 + lg + h * 8;
            if (r >= ne) continue;
            int col = n0 + wn * 32 + lt * 2;
            if (FUSED) {
                size_t base = (size_t)(off + r) * INTER + col;
                #pragma unroll
                for (int nf = 0; nf < 4; nf++) {
                    float g0 = accG[mf][nf][2*h],   g1 = accG[mf][nf][2*h+1];
                    float u0 = accU[mf][nf][2*h],   u1 = accU[mf][nf][2*h+1];
                    float h0 = g0 * sigmoidf_fast(g0) * u0;
                    float h1 = g1 * sigmoidf_fast(g1) * u1;
                    *(uint32_t*)(g_hh + base + nf * 8) = cvt2h(h0, h1);
                }
            } else {
                float* orow = g_y + (size_t)(off + r) * HIDDEN + col;
                #pragma unroll
                for (int nf = 0; nf < 4; nf++) {
                    float2 v = make_float2(accG[mf][nf][2*h], accG[mf][nf][2*h+1]);
                    *(float2*)(orow + nf * 8) = v;
                }
            }
        }
    }
}

// ---------------- combine ----------------
__global__ void combine_kernel(float* __restrict__ out) {
    int idx = blockIdx.x * blockDim.x + threadIdx.x;
    int t = idx / (HIDDEN / 4);
    int c = idx % (HIDDEN / 4);
    int e0 = g_te[2*t], e1 = g_te[2*t+1];
    size_t p0 = (size_t)g_off[e0] + g_tslot[2*t];
    size_t p1 = (size_t)g_off[e1] + g_tslot[2*t+1];
    float w0 = g_tw[2*t], w1 = g_tw[2*t+1];
    float4 y0 = *(const float4*)(g_y + p0 * HIDDEN + 4*c);
    float4 y1 = *(const float4*)(g_y + p1 * HIDDEN + 4*c);
    float4 r;
    r.x = w0*y0.x + w1*y1.x; r.y = w0*y0.y + w1*y1.y;
    r.z = w0*y0.z + w1*y1.z; r.w = w0*y0.w + w1*y1.w;
    *(float4*)(out + (size_t)t * HIDDEN + 4*c) = r;
}

// ---------------- launcher ----------------
extern "C" void kernel_launch(void* const* d_in, const int* in_sizes, int n_in,
                              void* d_out, int out_size) {
    const float* X   = (const float*)d_in[0];
    const float* Wg  = (const float*)d_in[1];
    const float* Wgp = (const float*)d_in[2];
    const float* Wup = (const float*)d_in[3];
    const float* Wdp = (const float*)d_in[4];
    float* out = (float*)d_out;

    __half *xh, *w0h, *w1h, *wdh, *hh;
    cudaGetSymbolAddress((void**)&xh,  c_Xh);
    cudaGetSymbolAddress((void**)&w0h, c_W0h);
    cudaGetSymbolAddress((void**)&w1h, c_W1h);
    cudaGetSymbolAddress((void**)&wdh, c_Wdh);
    cudaGetSymbolAddress((void**)&hh,  g_hh);

    constexpr int STAGE_F = (128*40 + 2*32*136) * 2;   // 27648 B
    constexpr int STAGE_D = (128*40 + 1*32*136) * 2;   // 18944 B
    const int SMEM_F = 3 * STAGE_F;                    // 82944
    const int SMEM_D = 3 * STAGE_D;                    // 56832
    cudaFuncSetAttribute(moe_gemm_fp16<1>, cudaFuncAttributeMaxDynamicSharedMemorySize, SMEM_F);
    cudaFuncSetAttribute(moe_gemm_fp16<0>, cudaFuncAttributeMaxDynamicSharedMemorySize, SMEM_D);

    // one-time stream/event setup (first call is the uncaptured correctness run)
    static cudaStream_t sAux = nullptr;
    static cudaEvent_t  evFork = nullptr, evX = nullptr, evWd = nullptr;
    if (sAux == nullptr) {
        cudaStreamCreateWithFlags(&sAux, cudaStreamNonBlocking);
        cudaEventCreateWithFlags(&evFork, cudaEventDisableTiming);
        cudaEventCreateWithFlags(&evX,    cudaEventDisableTiming);
        cudaEventCreateWithFlags(&evWd,   cudaEventDisableTiming);
    }

    const int NX = TOKENS * HIDDEN / 8;
    const int NW = EXPERTS * HIDDEN * INTER / 8;

    // ---- fork aux stream off the main (capture) stream ----
    cudaEventRecord(evFork, 0);
    cudaStreamWaitEvent(sAux, evFork, 0);

    // aux: routing + X conversion, then Wd conversion (overlaps fused GEMM)
    zero_cnt_kernel<<<1, 32, 0, sAux>>>();
    router_logits_kernel<<<(TOKENS * EXPERTS) / 256, 256, 0, sAux>>>(X, Wg);
    router_topk_kernel<<<(TOKENS + 255) / 256, 256, 0, sAux>>>();
    offsets_kernel<<<1, 1, 0, sAux>>>();
    cvt_kernel<<<(NX + 255) / 256, 256, 0, sAux>>>(X, xh, NX);
    cudaEventRecord(evX, sAux);
    cvt_kernel<<<(NW + 255) / 256, 256, 0, sAux>>>(Wdp, wdh, NW);
    cudaEventRecord(evWd, sAux);

    // main: gate/up weight conversion
    cvt_kernel<<<(NW + 255) / 256, 256>>>(Wgp, w0h, NW);
    cvt_kernel<<<(NW + 255) / 256, 256>>>(Wup, w1h, NW);

    // join: fused GEMM needs router + xh (+ w0h/w1h via stream order)
    cudaStreamWaitEvent(0, evX, 0);
    dim3 grid_f(TOKENS / 128, INTER / 128, EXPERTS);
    moe_gemm_fp16<1><<<grid_f, 256, SMEM_F>>>(xh, w0h, w1h);

    // join: down GEMM additionally needs wdh
    cudaStreamWaitEvent(0, evWd, 0);
    dim3 grid_d(TOKENS / 128, HIDDEN / 128, EXPERTS);
    moe_gemm_fp16<0><<<grid_d, 256, SMEM_D>>>(hh, wdh, nullptr);

    combine_kernel<<<(TOKENS * (HIDDEN / 4)) / 256, 256>>>(out);
}